// round 4
// baseline (speedup 1.0000x reference)
#include <cuda_runtime.h>
#include <cuda_bf16.h>
#include <math.h>

#define Bc 32
#define Nc 64
#define Fc 1280
#define Hc 512
#define Ec 512
#define Vc 10000
#define Tc 80
#define SOSc 1
#define G4 2048
#define NBLK 148
#define TPB 256
#define NTILE 157

// ---------------- device scratch ----------------
__device__ float g_h[2][Bc * Hc];
__device__ float g_c[2][Bc * Hc];
__device__ float g_x[Bc * Ec];
__device__ float g_hq[Bc * Hc];
__device__ float g_glin[Bc * Fc];
__device__ float g_ctx[Bc * Fc];
__device__ float g_encproj[Bc * Nc * Hc];
__device__ float g_mean[Bc * Fc];
__device__ float g_gacc[Bc * G4];
__device__ float g_pbv[NTILE * Bc];
__device__ int   g_pbi[NTILE * Bc];
__device__ unsigned g_bar;

#define HOFF ((size_t)Bc * Tc * Vc)
#define COFF (HOFF + (size_t)Bc * Hc)
#define AOFF (COFF + (size_t)Bc * Hc)

__device__ __forceinline__ float sigf(float x) { return 1.0f / (1.0f + expf(-x)); }

__device__ __forceinline__ void gridbar() {
    __threadfence();
    __syncthreads();
    if (threadIdx.x == 0) {
        unsigned t = atomicAdd(&g_bar, 1u) + 1u;
        unsigned target = ((t + NBLK - 1u) / NBLK) * NBLK;
        while (*((volatile unsigned*)&g_bar) < target) __nanosleep(64);
    }
    __syncthreads();
}

// ---------------- init kernels ----------------
__global__ void k_mean(const float* __restrict__ feat) {
    int idx = blockIdx.x * blockDim.x + threadIdx.x;
    if (idx >= Bc * Fc) return;
    int b = idx / Fc, f = idx % Fc;
    float s = 0.f;
    const float* p = feat + (size_t)b * Nc * Fc + f;
    for (int n = 0; n < Nc; n++) s += p[(size_t)n * Fc];
    g_mean[idx] = s * (1.0f / 64.0f);
}

__global__ void k_h0c0(const float* __restrict__ Wh, const float* __restrict__ bh,
                       const float* __restrict__ Wc, const float* __restrict__ bc) {
    int idx = blockIdx.x * blockDim.x + threadIdx.x;
    if (idx >= 2 * Bc * Hc) return;
    int half = idx / (Bc * Hc);
    int r = idx % (Bc * Hc);
    int b = r / Hc, j = r % Hc;
    const float* W = half ? Wc : Wh;
    float acc = half ? bc[j] : bh[j];
    const float* m = g_mean + b * Fc;
    for (int k = 0; k < Fc; k++) acc += m[k] * W[(size_t)k * Hc + j];
    if (half) g_c[0][r] = acc; else g_h[0][r] = acc;
}

__global__ void k_encproj(const float* __restrict__ feat, const float* __restrict__ W2,
                          const float* __restrict__ b2) {
    int tid = threadIdx.x;
    int rowbase = blockIdx.x * 64;
    int colbase = blockIdx.y * 64;
    int col = colbase + (tid & 63);
    int rgrp = tid >> 6;
    float acc[16];
#pragma unroll
    for (int i = 0; i < 16; i++) acc[i] = 0.f;
    __shared__ float As[64][33];
    __shared__ float Ws[32][65];
    for (int kc = 0; kc < Fc; kc += 32) {
        for (int e = tid; e < 64 * 32; e += 256) {
            int r = e >> 5, kk = e & 31;
            As[r][kk] = feat[(size_t)(rowbase + r) * Fc + kc + kk];
        }
        for (int e = tid; e < 32 * 64; e += 256) {
            int kk = e >> 6, c = e & 63;
            Ws[kk][c] = W2[(size_t)(kc + kk) * Hc + colbase + c];
        }
        __syncthreads();
        for (int kk = 0; kk < 32; kk++) {
            float w = Ws[kk][tid & 63];
#pragma unroll
            for (int i = 0; i < 16; i++) acc[i] += As[rgrp * 16 + i][kk] * w;
        }
        __syncthreads();
    }
    float bb = b2[col];
#pragma unroll
    for (int i = 0; i < 16; i++)
        g_encproj[(size_t)(rowbase + rgrp * 16 + i) * Hc + col] = acc[i] + bb;
}

__global__ void k_x0(const float* __restrict__ emb) {
    int idx = blockIdx.x * blockDim.x + threadIdx.x;
    if (idx == 0) g_bar = 0u;
    if (idx >= Bc * Ec) return;
    int e = idx % Ec;
    g_x[idx] = emb[(size_t)SOSc * Ec + e];
}

// ---------------- persistent kernel ----------------
__global__ void __launch_bounds__(TPB, 1) k_persist(
    const float* __restrict__ feat, const float* __restrict__ emb,
    const float* __restrict__ W1, const float* __restrict__ b1,
    const float* __restrict__ Va, const float* __restrict__ bVa,
    const float* __restrict__ Wg, const float* __restrict__ bg,
    const float* __restrict__ Wx, const float* __restrict__ Whh,
    const float* __restrict__ blstm, const float* __restrict__ Wout,
    const float* __restrict__ bout, float* __restrict__ dout)
{
    const int bid = blockIdx.x;
    const int tid = threadIdx.x;
    __shared__ float sm[64 * 36];   // transposed k-tiles: sm[kk*36 + b]
    __shared__ float sl[32 * 64];   // logits tile / hq staging / lstm gate exchange
    __shared__ float sred[TPB];
    __shared__ int   sredi[TPB];
    __shared__ float s_aux[4];

    for (int t = 0; t < Tc; t++) {
        const int rp = t & 1, wp = rp ^ 1;

        // ================= P1 =================
        if (bid < 32) {
            // finalize argmax of step t-1 -> x_t
            if (t > 0) {
                int b = bid;
                float bv = -INFINITY; int bi = 0x7fffffff;
                if (tid < NTILE) {
                    bv = __ldcg(&g_pbv[tid * 32 + b]);
                    bi = __ldcg(&g_pbi[tid * 32 + b]);
                }
                sred[tid] = bv; sredi[tid] = bi;
                __syncthreads();
                for (int o = 128; o; o >>= 1) {
                    if (tid < o) {
                        if (sred[tid + o] > sred[tid] ||
                            (sred[tid + o] == sred[tid] && sredi[tid + o] < sredi[tid])) {
                            sred[tid] = sred[tid + o];
                            sredi[tid] = sredi[tid + o];
                        }
                    }
                    __syncthreads();
                }
                int best = sredi[0];
                for (int e = tid; e < Ec; e += TPB)
                    g_x[b * Ec + e] = emb[(size_t)best * Ec + e];
            }
        } else if (bid < 60) {
            // hq (tiles 0..7) and glin (tiles 8..27): h @ {W1|Wg} + bias
            int colg = (bid - 32) * 64 + (tid & 63);
            int bgrp = tid >> 6;                 // 4 groups x 8 batches
            const float* Wcol; float bias; float* dst; int ldw;
            if (colg < Hc) { Wcol = W1 + colg; bias = b1[colg]; dst = g_hq + colg; ldw = Hc; }
            else { int cc = colg - Hc; Wcol = Wg + cc; bias = bg[cc]; dst = g_glin + cc; ldw = Fc; }
            float acc[8];
#pragma unroll
            for (int i = 0; i < 8; i++) acc[i] = 0.f;
            const float* hsrc = g_h[rp];
            for (int kc = 0; kc < Hc; kc += 64) {
                __syncthreads();
                for (int e = tid; e < 2048; e += TPB) {
                    int kk = e >> 5, b = e & 31;
                    sm[kk * 36 + b] = __ldcg(&hsrc[b * Hc + kc + kk]);
                }
                __syncthreads();
                for (int kk = 0; kk < 64; kk++) {
                    float w = Wcol[(size_t)(kc + kk) * ldw];
                    const float* xr = &sm[kk * 36 + bgrp * 8];
#pragma unroll
                    for (int i = 0; i < 8; i++) acc[i] = fmaf(xr[i], w, acc[i]);
                }
            }
#pragma unroll
            for (int i = 0; i < 8; i++) dst[(size_t)(bgrp * 8 + i) * ldw] = acc[i] + bias;
        } else if (bid < 124) {
            // gates h-part: h @ Whh -> g_gacc. 64 blocks x 32 cols, K=512
            int col = (bid - 60) * 32 + (tid & 31);
            int bg8 = tid >> 5;                  // 8 groups x 4 batches
            float acc[4] = {0.f, 0.f, 0.f, 0.f};
            const float* hsrc = g_h[rp];
            for (int kc = 0; kc < Hc; kc += 64) {
                __syncthreads();
                for (int e = tid; e < 2048; e += TPB) {
                    int kk = e >> 5, b = e & 31;
                    sm[kk * 36 + b] = __ldcg(&hsrc[b * Hc + kc + kk]);
                }
                __syncthreads();
                for (int kk = 0; kk < 64; kk++) {
                    float w = Whh[(size_t)(kc + kk) * G4 + col];
                    const float* xr = &sm[kk * 36 + bg8 * 4];
#pragma unroll
                    for (int i = 0; i < 4; i++) acc[i] = fmaf(xr[i], w, acc[i]);
                }
            }
#pragma unroll
            for (int i = 0; i < 4; i++) g_gacc[(bg8 * 4 + i) * G4 + col] = acc[i];
        }
        gridbar();

        // ================= P2: attention =================
        if (bid < 128) {
            int b = bid >> 2, sub = bid & 3;
            for (int k = tid; k < Hc; k += TPB) sl[k] = __ldcg(&g_hq[b * Hc + k]);
            __syncthreads();
            int warp = tid >> 5, lane = tid & 31;
            for (int n = warp; n < Nc; n += 8) {
                const float* ep = g_encproj + (size_t)(b * Nc + n) * Hc;
                float acc = 0.f;
                for (int k = lane; k < Hc; k += 32) {
                    float v = sl[k] + ep[k];
                    acc = fmaf(fmaxf(v, 0.f), Va[k], acc);
                }
#pragma unroll
                for (int o = 16; o; o >>= 1) acc += __shfl_down_sync(0xffffffffu, acc, o);
                if (lane == 0) sred[n] = acc + bVa[0];
            }
            __syncthreads();
            float sc = (tid < Nc) ? sred[tid] : -INFINITY;
            if (tid < Nc) {
                float m = sc;
#pragma unroll
                for (int o = 16; o; o >>= 1) m = fmaxf(m, __shfl_xor_sync(0xffffffffu, m, o));
                if ((tid & 31) == 0) s_aux[tid >> 5] = m;
            }
            __syncthreads();
            float M = fmaxf(s_aux[0], s_aux[1]);
            if (tid < Nc) {
                float e = expf(sc - M);
                sred[tid] = e;
                float ss = e;
#pragma unroll
                for (int o = 16; o; o >>= 1) ss += __shfl_xor_sync(0xffffffffu, ss, o);
                if ((tid & 31) == 0) s_aux[2 + (tid >> 5)] = ss;
            }
            __syncthreads();
            float inv = 1.0f / (s_aux[2] + s_aux[3]);
            if (tid < Nc) {
                float wv = sred[tid] * inv;
                sred[tid] = wv;
                if (sub == 0)
                    dout[AOFF + (size_t)b * Tc * Nc + (size_t)t * Nc + tid] = wv;
            }
            __syncthreads();
            int fbase = sub * 320;
            for (int f = fbase + tid; f < fbase + 320; f += TPB) {
                const float* fb = feat + (size_t)b * Nc * Fc + f;
                float acc = 0.f;
#pragma unroll 8
                for (int n = 0; n < Nc; n++) acc = fmaf(fb[(size_t)n * Fc], sred[n], acc);
                g_ctx[b * Fc + f] = acc * sigf(__ldcg(&g_glin[b * Fc + f]));
            }
        }
        gridbar();

        // ================= P3: gates (x,ctx) + LSTM pointwise =================
        if (bid < 128) {
            int j0 = bid * 4;
            int ci = tid & 15, bp = tid >> 4;    // 16 cols, 16 pairs of batches
            int gate = ci >> 2, jj = ci & 3;
            int col = gate * Hc + j0 + jj;
            float acc0 = 0.f, acc1 = 0.f;
            for (int kc = 0; kc < 1792; kc += 64) {
                __syncthreads();
                for (int e = tid; e < 2048; e += TPB) {
                    int kk = e >> 5, b = e & 31;
                    int k = kc + kk;
                    sm[kk * 36 + b] = (k < Ec) ? __ldcg(&g_x[b * Ec + k])
                                               : __ldcg(&g_ctx[b * Fc + (k - Ec)]);
                }
                __syncthreads();
                for (int kk = 0; kk < 64; kk++) {
                    float w = Wx[(size_t)(kc + kk) * G4 + col];
                    const float* xr = &sm[kk * 36 + bp * 2];
                    acc0 = fmaf(xr[0], w, acc0);
                    acc1 = fmaf(xr[1], w, acc1);
                }
            }
            float bl = blstm[col];
            sl[(bp * 2 + 0) * 16 + ci] = acc0 + __ldcg(&g_gacc[(bp * 2 + 0) * G4 + col]) + bl;
            sl[(bp * 2 + 1) * 16 + ci] = acc1 + __ldcg(&g_gacc[(bp * 2 + 1) * G4 + col]) + bl;
            __syncthreads();
            if (tid < 128) {
                int b = tid >> 2, jj2 = tid & 3;
                float gi = sl[b * 16 + 0 * 4 + jj2];
                float gf = sl[b * 16 + 1 * 4 + jj2];
                float gg = sl[b * 16 + 2 * 4 + jj2];
                float go = sl[b * 16 + 3 * 4 + jj2];
                int j = j0 + jj2;
                float cprev = g_c[rp][b * Hc + j];
                float iv = sigf(gi), fv = sigf(gf), gv = tanhf(gg), ov = sigf(go);
                float c2 = fv * cprev + iv * gv;
                float h2 = ov * tanhf(c2);
                g_c[wp][b * Hc + j] = c2;
                g_h[wp][b * Hc + j] = h2;
            }
        }
        gridbar();

        // ================= P4: logits + per-tile partial argmax =================
        for (int tile = bid; tile < NTILE; tile += NBLK) {
            int c63 = tid & 63;
            int col = tile * 64 + c63;
            int colc = (col < Vc) ? col : (Vc - 1);
            int bgrp = tid >> 6;
            float acc[8];
#pragma unroll
            for (int i = 0; i < 8; i++) acc[i] = 0.f;
            const float* hsrc = g_h[wp];
            for (int kc = 0; kc < Hc; kc += 64) {
                __syncthreads();
                for (int e = tid; e < 2048; e += TPB) {
                    int kk = e >> 5, b = e & 31;
                    sm[kk * 36 + b] = __ldcg(&hsrc[b * Hc + kc + kk]);
                }
                __syncthreads();
                for (int kk = 0; kk < 64; kk++) {
                    float w = Wout[(size_t)(kc + kk) * Vc + colc];
                    const float* xr = &sm[kk * 36 + bgrp * 8];
#pragma unroll
                    for (int i = 0; i < 8; i++) acc[i] = fmaf(xr[i], w, acc[i]);
                }
            }
            float bo = bout[colc];
            bool valid = (col < Vc);
#pragma unroll
            for (int i = 0; i < 8; i++) {
                float v = acc[i] + bo;
                int b = bgrp * 8 + i;
                if (valid)
                    dout[(size_t)b * Tc * Vc + (size_t)t * Vc + col] = v;
                sl[b * 64 + c63] = valid ? v : -INFINITY;
            }
            __syncthreads();
            if (tid < 32) {
                int b = tid;
                float bv = -INFINITY; int bi = 0;
                for (int cq = 0; cq < 64; cq++) {
                    float v = sl[b * 64 + cq];
                    if (v > bv) { bv = v; bi = tile * 64 + cq; }
                }
                g_pbv[tile * 32 + b] = bv;
                g_pbi[tile * 32 + b] = bi;
            }
            __syncthreads();
        }
        if (t == Tc - 1) {
            int gid = bid * TPB + tid;
            if (gid < Bc * Hc) {
                dout[HOFF + gid] = __ldcg(&g_h[wp][gid]);
                dout[COFF + gid] = __ldcg(&g_c[wp][gid]);
            }
        }
        gridbar();
    }
}

// ---------------- launcher ----------------
extern "C" void kernel_launch(void* const* d_in, const int* in_sizes, int n_in,
                              void* d_out, int out_size) {
    int off = (n_in > 2 && in_sizes[2] == 1) ? 1 : 0;
    const float* feat  = (const float*)d_in[0];
    const float* emb   = (const float*)d_in[2 + off];
    const float* W1    = (const float*)d_in[3 + off];
    const float* b1    = (const float*)d_in[4 + off];
    const float* W2    = (const float*)d_in[5 + off];
    const float* b2    = (const float*)d_in[6 + off];
    const float* Va    = (const float*)d_in[7 + off];
    const float* bVa   = (const float*)d_in[8 + off];
    const float* Wh    = (const float*)d_in[9 + off];
    const float* bh    = (const float*)d_in[10 + off];
    const float* Wc    = (const float*)d_in[11 + off];
    const float* bc    = (const float*)d_in[12 + off];
    const float* Wg    = (const float*)d_in[13 + off];
    const float* bg    = (const float*)d_in[14 + off];
    const float* Wx    = (const float*)d_in[15 + off];
    const float* Whh   = (const float*)d_in[16 + off];
    const float* blstm = (const float*)d_in[17 + off];
    const float* Wout  = (const float*)d_in[18 + off];
    const float* bout  = (const float*)d_in[19 + off];
    float* out = (float*)d_out;

    k_mean<<<(Bc * Fc + 255) / 256, 256>>>(feat);
    k_h0c0<<<(2 * Bc * Hc + 255) / 256, 256>>>(Wh, bh, Wc, bc);
    k_encproj<<<dim3(32, 8), 256>>>(feat, W2, b2);
    k_x0<<<(Bc * Ec + 255) / 256, 256>>>(emb);

    k_persist<<<NBLK, TPB>>>(feat, emb, W1, b1, Va, bVa, Wg, bg,
                             Wx, Whh, blstm, Wout, bout, out);
}

// round 5
// speedup vs baseline: 1.8289x; 1.8289x over previous
#include <cuda_runtime.h>
#include <cuda_bf16.h>
#include <math.h>

#define Bc 32
#define Nc 64
#define Fc 1280
#define Hc 512
#define Ec 512
#define Vc 10000
#define Tc 80
#define SOSc 1
#define G4 2048
#define NBLK 148
#define TPB 512
#define NTILE 157

typedef unsigned long long ull;

// ---------------- device scratch ----------------
__device__ float g_h[2][Bc * Hc];
__device__ float g_c[2][Bc * Hc];
__device__ float g_x[Bc * Ec];
__device__ float g_hq[Bc * Hc];
__device__ float g_glin[Bc * Fc];
__device__ float g_ctx[Bc * Fc];
__device__ float g_encproj[Bc * Nc * Hc];
__device__ float g_mean[Bc * Fc];
__device__ float g_gp[6][Bc * G4];
__device__ float g_pbv[NTILE * Bc];
__device__ int   g_pbi[NTILE * Bc];
__device__ unsigned g_bar;

#define HOFF ((size_t)Bc * Tc * Vc)
#define COFF (HOFF + (size_t)Bc * Hc)
#define AOFF (COFF + (size_t)Bc * Hc)

__device__ __forceinline__ float sigf(float x) { return 1.0f / (1.0f + expf(-x)); }

// packed f32x2 helpers (FFMA2 path — ptxas never emits it from plain C++)
__device__ __forceinline__ ull pk2(float x) {
    ull r; asm("mov.b64 %0,{%1,%1};" : "=l"(r) : "r"(__float_as_uint(x))); return r;
}
__device__ __forceinline__ ull mk2(float x, float y) {
    ull r; asm("mov.b64 %0,{%1,%2};" : "=l"(r) : "r"(__float_as_uint(x)), "r"(__float_as_uint(y)));
    return r;
}
__device__ __forceinline__ void fma2(ull& d, ull a, ull b) {
    asm("fma.rn.f32x2 %0,%1,%2,%0;" : "+l"(d) : "l"(a), "l"(b));
}
__device__ __forceinline__ float2 un2(ull v) {
    unsigned lo, hi; asm("mov.b64 {%0,%1},%2;" : "=r"(lo), "=r"(hi) : "l"(v));
    float2 f; f.x = __uint_as_float(lo); f.y = __uint_as_float(hi); return f;
}

__device__ __forceinline__ void gridbar() {
    __threadfence();
    __syncthreads();
    if (threadIdx.x == 0) {
        unsigned t = atomicAdd(&g_bar, 1u) + 1u;
        unsigned target = ((t + NBLK - 1u) / NBLK) * NBLK;
        while (*((volatile unsigned*)&g_bar) < target) __nanosleep(32);
    }
    __syncthreads();
}

// ---------------- init kernels ----------------
__global__ void k_mean(const float* __restrict__ feat) {
    int idx = blockIdx.x * blockDim.x + threadIdx.x;
    if (idx >= Bc * Fc) return;
    int b = idx / Fc, f = idx % Fc;
    float s = 0.f;
    const float* p = feat + (size_t)b * Nc * Fc + f;
#pragma unroll 8
    for (int n = 0; n < Nc; n++) s += p[(size_t)n * Fc];
    g_mean[idx] = s * (1.0f / 64.0f);
}

// h0/c0: [32 x 1280] @ [1280 x (512|512)], tiled. grid 16 x 256
__global__ void k_h0c0(const float* __restrict__ Wh, const float* __restrict__ bh,
                       const float* __restrict__ Wc, const float* __restrict__ bc) {
    __shared__ __align__(16) float sm[64 * 36];
    int tid = threadIdx.x;
    int colg = blockIdx.x * 64 + (tid & 63);
    int bgrp = tid >> 6;  // 0..3, 8 batches each
    float acc[8] = {0, 0, 0, 0, 0, 0, 0, 0};
    const float* W; float bias; float* dst;
    if (colg < Hc) { W = Wh + colg; bias = bh[colg]; dst = g_h[0] + colg; }
    else { W = Wc + (colg - Hc); bias = bc[colg - Hc]; dst = g_c[0] + (colg - Hc); }
    for (int kc = 0; kc < Fc; kc += 64) {
        __syncthreads();
        for (int e = tid; e < 2048; e += 256) {
            int kk = e >> 5, b = e & 31;
            sm[kk * 36 + b] = g_mean[b * Fc + kc + kk];
        }
        __syncthreads();
#pragma unroll 8
        for (int kk = 0; kk < 64; kk++) {
            float w = W[(size_t)(kc + kk) * Hc];
            const float* xr = &sm[kk * 36 + bgrp * 8];
#pragma unroll
            for (int i = 0; i < 8; i++) acc[i] = fmaf(xr[i], w, acc[i]);
        }
    }
#pragma unroll
    for (int i = 0; i < 8; i++) dst[(bgrp * 8 + i) * Hc] = acc[i] + bias;
}

__global__ void k_encproj(const float* __restrict__ feat, const float* __restrict__ W2,
                          const float* __restrict__ b2) {
    int tid = threadIdx.x;
    int rowbase = blockIdx.x * 64;
    int colbase = blockIdx.y * 64;
    int col = colbase + (tid & 63);
    int rgrp = tid >> 6;
    float acc[16];
#pragma unroll
    for (int i = 0; i < 16; i++) acc[i] = 0.f;
    __shared__ float As[64][33];
    __shared__ float Ws[32][65];
    for (int kc = 0; kc < Fc; kc += 32) {
        for (int e = tid; e < 64 * 32; e += 256) {
            int r = e >> 5, kk = e & 31;
            As[r][kk] = feat[(size_t)(rowbase + r) * Fc + kc + kk];
        }
        for (int e = tid; e < 32 * 64; e += 256) {
            int kk = e >> 6, c = e & 63;
            Ws[kk][c] = W2[(size_t)(kc + kk) * Hc + colbase + c];
        }
        __syncthreads();
#pragma unroll 8
        for (int kk = 0; kk < 32; kk++) {
            float w = Ws[kk][tid & 63];
#pragma unroll
            for (int i = 0; i < 16; i++) acc[i] += As[rgrp * 16 + i][kk] * w;
        }
        __syncthreads();
    }
    float bb = b2[col];
#pragma unroll
    for (int i = 0; i < 16; i++)
        g_encproj[(size_t)(rowbase + rgrp * 16 + i) * Hc + col] = acc[i] + bb;
}

__global__ void k_x0(const float* __restrict__ emb) {
    int idx = blockIdx.x * blockDim.x + threadIdx.x;
    if (idx == 0) g_bar = 0u;
    if (idx >= Bc * Ec) return;
    g_x[idx] = emb[(size_t)SOSc * Ec + (idx % Ec)];
}

// ---------------- persistent kernel ----------------
__global__ void __launch_bounds__(TPB, 1) k_persist(
    const float* __restrict__ feat, const float* __restrict__ emb,
    const float* __restrict__ W1, const float* __restrict__ b1,
    const float* __restrict__ Va, const float* __restrict__ bVa,
    const float* __restrict__ Wg, const float* __restrict__ bg,
    const float* __restrict__ Wx, const float* __restrict__ Whh,
    const float* __restrict__ blstm, const float* __restrict__ Wout,
    const float* __restrict__ bout, float* __restrict__ dout)
{
    const int bid = blockIdx.x;
    const int tid = threadIdx.x;
    __shared__ __align__(16) float sm[64 * 36];   // staged k-tile, transposed: sm[kk*36 + b]
    __shared__ float sl[2048];                     // logits tile / hq staging
    __shared__ float sred[TPB];
    __shared__ int   sredi[TPB];
    __shared__ float s_aux[4];

    const int c63 = tid & 63;
    const int bg4 = (tid >> 6) * 4;   // 8 batch-groups of 4

    for (int t = 0; t < Tc; t++) {
        const int rp = t & 1, wp = rp ^ 1;

        // ================= P1: argmax-finalize | hq+glin | gates h-part =================
        if (bid < 32) {
            if (t > 0) {
                int b = bid;
                float bv = -INFINITY; int bi = 0x7fffffff;
                if (tid < NTILE) {
                    bv = __ldcg(&g_pbv[tid * 32 + b]);
                    bi = __ldcg(&g_pbi[tid * 32 + b]);
                }
                sred[tid] = bv; sredi[tid] = bi;
                __syncthreads();
                for (int o = 256; o; o >>= 1) {
                    if (tid < o) {
                        if (sred[tid + o] > sred[tid] ||
                            (sred[tid + o] == sred[tid] && sredi[tid + o] < sredi[tid])) {
                            sred[tid] = sred[tid + o];
                            sredi[tid] = sredi[tid + o];
                        }
                    }
                    __syncthreads();
                }
                int best = sredi[0];
                g_x[b * Ec + tid] = emb[(size_t)best * Ec + tid];   // Ec == TPB
            }
        } else if (bid < 60) {
            // hq (cols 0..511) / glin (cols 512..1791): h @ {W1|Wg}
            int colg = (bid - 32) * 64 + c63;
            const float* Wp; float bias; float* dst; int ldw;
            if (colg < Hc) { Wp = W1 + colg; bias = b1[colg]; dst = g_hq + colg; ldw = Hc; }
            else { int cc = colg - Hc; Wp = Wg + cc; bias = bg[cc]; dst = g_glin + cc; ldw = Fc; }
            ull a0 = 0, a1 = 0;
            const float* hsrc = g_h[rp];
            for (int kc = 0; kc < Hc; kc += 64) {
                __syncthreads();
                for (int e = tid; e < 2048; e += TPB) {
                    int kk = e >> 5, b = e & 31;
                    sm[kk * 36 + b] = __ldcg(&hsrc[b * Hc + kc + kk]);
                }
                __syncthreads();
#pragma unroll 8
                for (int kk = 0; kk < 64; kk++) {
                    float w = Wp[(size_t)(kc + kk) * ldw];
                    ull w2 = pk2(w);
                    float4 v = *(const float4*)&sm[kk * 36 + bg4];
                    fma2(a0, mk2(v.x, v.y), w2);
                    fma2(a1, mk2(v.z, v.w), w2);
                }
            }
            float2 p0 = un2(a0), p1 = un2(a1);
            dst[(size_t)(bg4 + 0) * ldw] = p0.x + bias;
            dst[(size_t)(bg4 + 1) * ldw] = p0.y + bias;
            dst[(size_t)(bg4 + 2) * ldw] = p1.x + bias;
            dst[(size_t)(bg4 + 3) * ldw] = p1.y + bias;
        } else if (bid < 124) {
            // gates h-part: h @ Whh, 32 col-tiles x 2 K-halves
            int u = bid - 60;
            int tile = u >> 1, kh = u & 1;
            int col = tile * 64 + c63;
            ull a0 = 0, a1 = 0;
            const float* hsrc = g_h[rp];
            int k0 = kh * 256;
            for (int kc = k0; kc < k0 + 256; kc += 64) {
                __syncthreads();
                for (int e = tid; e < 2048; e += TPB) {
                    int kk = e >> 5, b = e & 31;
                    sm[kk * 36 + b] = __ldcg(&hsrc[b * Hc + kc + kk]);
                }
                __syncthreads();
#pragma unroll 8
                for (int kk = 0; kk < 64; kk++) {
                    float w = Whh[(size_t)(kc + kk) * G4 + col];
                    ull w2 = pk2(w);
                    float4 v = *(const float4*)&sm[kk * 36 + bg4];
                    fma2(a0, mk2(v.x, v.y), w2);
                    fma2(a1, mk2(v.z, v.w), w2);
                }
            }
            float2 p0 = un2(a0), p1 = un2(a1);
            float* gp = g_gp[kh];
            gp[(bg4 + 0) * G4 + col] = p0.x;
            gp[(bg4 + 1) * G4 + col] = p0.y;
            gp[(bg4 + 2) * G4 + col] = p1.x;
            gp[(bg4 + 3) * G4 + col] = p1.y;
        }
        gridbar();

        // ================= P2: attention (4 blocks per batch row) =================
        if (bid < 128) {
            int b = bid >> 2, sub = bid & 3;
            for (int k = tid; k < Hc; k += TPB) sl[k] = __ldcg(&g_hq[b * Hc + k]);
            __syncthreads();
            int warp = tid >> 5, lane = tid & 31;
#pragma unroll
            for (int ni = 0; ni < 4; ni++) {
                int n = warp + ni * 16;
                const float* ep = g_encproj + (size_t)(b * Nc + n) * Hc;
                float acc = 0.f;
#pragma unroll 4
                for (int k = lane; k < Hc; k += 32) {
                    float v = sl[k] + ep[k];
                    acc = fmaf(fmaxf(v, 0.f), Va[k], acc);
                }
#pragma unroll
                for (int o = 16; o; o >>= 1) acc += __shfl_down_sync(0xffffffffu, acc, o);
                if (lane == 0) sred[n] = acc + bVa[0];
            }
            __syncthreads();
            if (tid < 64) {
                float m = sred[tid];
#pragma unroll
                for (int o = 16; o; o >>= 1) m = fmaxf(m, __shfl_xor_sync(0xffffffffu, m, o));
                if (lane == 0) s_aux[tid >> 5] = m;
            }
            __syncthreads();
            if (tid < 64) {
                float M = fmaxf(s_aux[0], s_aux[1]);
                float e = expf(sred[tid] - M);
                sred[tid] = e;
                float ss = e;
#pragma unroll
                for (int o = 16; o; o >>= 1) ss += __shfl_xor_sync(0xffffffffu, ss, o);
                if (lane == 0) s_aux[2 + (tid >> 5)] = ss;
            }
            __syncthreads();
            if (tid < 64) {
                float wv = sred[tid] / (s_aux[2] + s_aux[3]);
                sred[tid] = wv;
                if (sub == 0)
                    dout[AOFF + (size_t)b * Tc * Nc + (size_t)t * Nc + tid] = wv;
            }
            __syncthreads();
            if (tid < 320) {
                int f = sub * 320 + tid;
                const float* fb = feat + (size_t)b * Nc * Fc + f;
                float acc = 0.f;
#pragma unroll 8
                for (int n = 0; n < 64; n++) acc = fmaf(fb[(size_t)n * Fc], sred[n], acc);
                g_ctx[b * Fc + f] = acc * sigf(__ldcg(&g_glin[b * Fc + f]));
            }
        }
        gridbar();

        // ================= P3: gates x/ctx part, 32 col-tiles x 4 K-chunks =================
        if (bid < 128) {
            int tile = bid >> 2, kq = bid & 3;
            int col = tile * 64 + c63;
            int kbase = kq * 448;
            ull a0 = 0, a1 = 0;
            for (int kc = 0; kc < 448; kc += 64) {
                __syncthreads();
                for (int e = tid; e < 2048; e += TPB) {
                    int kk = e >> 5, b = e & 31;
                    int k = kbase + kc + kk;
                    sm[kk * 36 + b] = (k < Ec) ? __ldcg(&g_x[b * Ec + k])
                                               : __ldcg(&g_ctx[b * Fc + (k - Ec)]);
                }
                __syncthreads();
#pragma unroll 8
                for (int kk = 0; kk < 64; kk++) {
                    float w = Wx[(size_t)(kbase + kc + kk) * G4 + col];
                    ull w2 = pk2(w);
                    float4 v = *(const float4*)&sm[kk * 36 + bg4];
                    fma2(a0, mk2(v.x, v.y), w2);
                    fma2(a1, mk2(v.z, v.w), w2);
                }
            }
            float2 p0 = un2(a0), p1 = un2(a1);
            float* gp = g_gp[2 + kq];
            gp[(bg4 + 0) * G4 + col] = p0.x;
            gp[(bg4 + 1) * G4 + col] = p0.y;
            gp[(bg4 + 2) * G4 + col] = p1.x;
            gp[(bg4 + 3) * G4 + col] = p1.y;
        }
        gridbar();

        // ================= P3b: LSTM pointwise (reduce 6 partials) =================
        if (bid < 32) {
            int id = bid * TPB + tid;          // 0..16383
            int b = id >> 9, j = id & 511;
            float gi = blstm[j], gf = blstm[Hc + j], gg = blstm[2 * Hc + j], go = blstm[3 * Hc + j];
#pragma unroll
            for (int p = 0; p < 6; p++) {
                const float* gp = g_gp[p] + b * G4;
                gi += __ldcg(&gp[j]);
                gf += __ldcg(&gp[Hc + j]);
                gg += __ldcg(&gp[2 * Hc + j]);
                go += __ldcg(&gp[3 * Hc + j]);
            }
            float cprev = g_c[rp][b * Hc + j];
            float iv = sigf(gi), fv = sigf(gf), gv = tanhf(gg), ov = sigf(go);
            float c2 = fv * cprev + iv * gv;
            float h2 = ov * tanhf(c2);
            g_c[wp][b * Hc + j] = c2;
            g_h[wp][b * Hc + j] = h2;
            if (t == Tc - 1) {
                dout[HOFF + b * Hc + j] = h2;
                dout[COFF + b * Hc + j] = c2;
            }
        }
        gridbar();

        // ================= P4: logits + per-tile partial argmax =================
        for (int tile = bid; tile < NTILE; tile += NBLK) {
            int col = tile * 64 + c63;
            int colc = (col < Vc) ? col : (Vc - 1);
            ull a0 = 0, a1 = 0;
            const float* hsrc = g_h[wp];
            for (int kc = 0; kc < Hc; kc += 64) {
                __syncthreads();
                for (int e = tid; e < 2048; e += TPB) {
                    int kk = e >> 5, b = e & 31;
                    sm[kk * 36 + b] = __ldcg(&hsrc[b * Hc + kc + kk]);
                }
                __syncthreads();
#pragma unroll 8
                for (int kk = 0; kk < 64; kk++) {
                    float w = Wout[(size_t)(kc + kk) * Vc + colc];
                    ull w2 = pk2(w);
                    float4 v = *(const float4*)&sm[kk * 36 + bg4];
                    fma2(a0, mk2(v.x, v.y), w2);
                    fma2(a1, mk2(v.z, v.w), w2);
                }
            }
            float bo = bout[colc];
            float2 p0 = un2(a0), p1 = un2(a1);
            float vv[4] = {p0.x + bo, p0.y + bo, p1.x + bo, p1.y + bo};
            bool valid = (col < Vc);
#pragma unroll
            for (int i = 0; i < 4; i++) {
                int b = bg4 + i;
                if (valid)
                    dout[(size_t)b * Tc * Vc + (size_t)t * Vc + col] = vv[i];
                sl[b * 64 + c63] = valid ? vv[i] : -INFINITY;
            }
            __syncthreads();
            if (tid < 32) {
                int b = tid;
                float bv = -INFINITY; int bi = 0;
#pragma unroll 8
                for (int cq = 0; cq < 64; cq++) {
                    float v = sl[b * 64 + cq];
                    if (v > bv) { bv = v; bi = tile * 64 + cq; }
                }
                g_pbv[tile * 32 + b] = bv;
                g_pbi[tile * 32 + b] = bi;
            }
            __syncthreads();
        }
        gridbar();
    }
}

// ---------------- launcher ----------------
extern "C" void kernel_launch(void* const* d_in, const int* in_sizes, int n_in,
                              void* d_out, int out_size) {
    int off = (n_in > 2 && in_sizes[2] == 1) ? 1 : 0;
    const float* feat  = (const float*)d_in[0];
    const float* emb   = (const float*)d_in[2 + off];
    const float* W1    = (const float*)d_in[3 + off];
    const float* b1    = (const float*)d_in[4 + off];
    const float* W2    = (const float*)d_in[5 + off];
    const float* b2    = (const float*)d_in[6 + off];
    const float* Va    = (const float*)d_in[7 + off];
    const float* bVa   = (const float*)d_in[8 + off];
    const float* Wh    = (const float*)d_in[9 + off];
    const float* bh    = (const float*)d_in[10 + off];
    const float* Wc    = (const float*)d_in[11 + off];
    const float* bc    = (const float*)d_in[12 + off];
    const float* Wg    = (const float*)d_in[13 + off];
    const float* bg    = (const float*)d_in[14 + off];
    const float* Wx    = (const float*)d_in[15 + off];
    const float* Whh   = (const float*)d_in[16 + off];
    const float* blstm = (const float*)d_in[17 + off];
    const float* Wout  = (const float*)d_in[18 + off];
    const float* bout  = (const float*)d_in[19 + off];
    float* out = (float*)d_out;

    k_mean<<<(Bc * Fc + 255) / 256, 256>>>(feat);
    k_h0c0<<<16, 256>>>(Wh, bh, Wc, bc);
    k_encproj<<<dim3(32, 8), 256>>>(feat, W2, b2);
    k_x0<<<(Bc * Ec + 255) / 256, 256>>>(emb);

    k_persist<<<NBLK, TPB>>>(feat, emb, W1, b1, Va, bVa, Wg, bg,
                             Wx, Whh, blstm, Wout, bout, out);
}

// round 6
// speedup vs baseline: 3.1280x; 1.7103x over previous
#include <cuda_runtime.h>
#include <cuda_bf16.h>
#include <math.h>

#define Bc 32
#define Nc 64
#define Fc 1280
#define Hc 512
#define Ec 512
#define Vc 10000
#define Tc 80
#define SOSc 1
#define G4 2048
#define NBLK 148
#define TPB 512
#define LPW 10112
#define NT79 79

typedef unsigned long long ull;

// ---------------- device scratch ----------------
__device__ float g_h[2][Bc * Hc];
__device__ float g_c[2][Bc * Hc];
__device__ float g_x[Bc * Ec];
__device__ float g_hqp[4][Bc * Hc];    // hq partials (K-split 4)
__device__ float g_glp[4][Bc * Fc];    // glin partials
__device__ float g_ctx[Bc * Fc];
__device__ float g_encproj[Bc * Nc * Hc];
__device__ float g_mean[Bc * Fc];
__device__ float g_gp[11][Bc * G4];    // gates partials: 0..3 h-part, 4..10 x-part
__device__ float g_lp[2][Bc * LPW];    // logits partials (K-split 2)
__device__ float g_pbv[NT79 * Bc];
__device__ int   g_pbi[NT79 * Bc];
__device__ unsigned g_bar;

#define HOFF ((size_t)Bc * Tc * Vc)
#define COFF (HOFF + (size_t)Bc * Hc)
#define AOFF (COFF + (size_t)Bc * Hc)

__device__ __forceinline__ float sigf(float x) { return 1.0f / (1.0f + expf(-x)); }

// packed f32x2 helpers
__device__ __forceinline__ ull pk2(float x) {
    ull r; asm("mov.b64 %0,{%1,%1};" : "=l"(r) : "r"(__float_as_uint(x))); return r;
}
__device__ __forceinline__ void fma2(ull& d, ull a, ull b) {
    asm("fma.rn.f32x2 %0,%1,%2,%0;" : "+l"(d) : "l"(a), "l"(b));
}
__device__ __forceinline__ float2 un2(ull v) {
    unsigned lo, hi; asm("mov.b64 {%0,%1},%2;" : "=r"(lo), "=r"(hi) : "l"(v));
    float2 f; f.x = __uint_as_float(lo); f.y = __uint_as_float(hi); return f;
}

__device__ __forceinline__ void gridbar() {
    __syncthreads();
    if (threadIdx.x == 0) {
        __threadfence();
        unsigned t = atomicAdd(&g_bar, 1u) + 1u;
        unsigned target = ((t + NBLK - 1u) / NBLK) * NBLK;
        while (*((volatile unsigned*)&g_bar) < target) __nanosleep(64);
        __threadfence();
    }
    __syncthreads();
}

// stage 64 k-values x 32 batches, transposed: sm[kk*36 + b]
__device__ __forceinline__ void stage_g(float* sm, const float* __restrict__ src,
                                        int kc, int stride, int tid) {
#pragma unroll
    for (int e = tid; e < 2048; e += TPB) {
        int kk = e >> 5, b = e & 31;
        sm[kk * 36 + b] = __ldcg(&src[b * stride + kc + kk]);
    }
}

// one 64-kk chunk of batch-tiled GEMM: 8 batches/thread, weights two-phase (MLP=8)
__device__ __forceinline__ void gemm_chunk(const float* __restrict__ Wp, size_t ldw,
                                           const float* sm, int bg8,
                                           ull& a0, ull& a1, ull& a2, ull& a3) {
#pragma unroll
    for (int kk8 = 0; kk8 < 64; kk8 += 8) {
        float wv[8];
#pragma unroll
        for (int u = 0; u < 8; u++) wv[u] = Wp[(size_t)(kk8 + u) * ldw];
#pragma unroll
        for (int u = 0; u < 8; u++) {
            ull w2 = pk2(wv[u]);
            const float* base = sm + (kk8 + u) * 36 + bg8;
            ulonglong2 lv0 = *(const ulonglong2*)(base);
            ulonglong2 lv1 = *(const ulonglong2*)(base + 4);
            fma2(a0, lv0.x, w2); fma2(a1, lv0.y, w2);
            fma2(a2, lv1.x, w2); fma2(a3, lv1.y, w2);
        }
    }
}

// ---------------- init kernels (3 launches before persist) ----------------
__global__ void k_mean(const float* __restrict__ feat, const float* __restrict__ emb) {
    int idx = blockIdx.x * blockDim.x + threadIdx.x;
    if (idx == 0) g_bar = 0u;
    if (idx < Bc * Ec) g_x[idx] = emb[(size_t)SOSc * Ec + (idx % Ec)];
    if (idx >= Bc * Fc) return;
    int b = idx / Fc, f = idx % Fc;
    float s = 0.f;
    const float* p = feat + (size_t)b * Nc * Fc + f;
#pragma unroll 8
    for (int n = 0; n < Nc; n++) s += p[(size_t)n * Fc];
    g_mean[idx] = s * (1.0f / 64.0f);
}

__global__ void k_h0c0(const float* __restrict__ Wh, const float* __restrict__ bh,
                       const float* __restrict__ Wc, const float* __restrict__ bc) {
    __shared__ __align__(16) float sm[64 * 36];
    int tid = threadIdx.x;
    int colg = blockIdx.x * 64 + (tid & 63);
    int bgrp = tid >> 6;
    float acc[8] = {0, 0, 0, 0, 0, 0, 0, 0};
    const float* W; float bias; float* dst;
    if (colg < Hc) { W = Wh + colg; bias = bh[colg]; dst = g_h[0] + colg; }
    else { W = Wc + (colg - Hc); bias = bc[colg - Hc]; dst = g_c[0] + (colg - Hc); }
    for (int kc = 0; kc < Fc; kc += 64) {
        __syncthreads();
        for (int e = tid; e < 2048; e += 256) {
            int kk = e >> 5, b = e & 31;
            sm[kk * 36 + b] = g_mean[b * Fc + kc + kk];
        }
        __syncthreads();
#pragma unroll 8
        for (int kk = 0; kk < 64; kk++) {
            float w = W[(size_t)(kc + kk) * Hc];
            const float* xr = &sm[kk * 36 + bgrp * 8];
#pragma unroll
            for (int i = 0; i < 8; i++) acc[i] = fmaf(xr[i], w, acc[i]);
        }
    }
#pragma unroll
    for (int i = 0; i < 8; i++) dst[(bgrp * 8 + i) * Hc] = acc[i] + bias;
}

__global__ void k_encproj(const float* __restrict__ feat, const float* __restrict__ W2,
                          const float* __restrict__ b2) {
    int tid = threadIdx.x;
    int rowbase = blockIdx.x * 64;
    int colbase = blockIdx.y * 64;
    int col = colbase + (tid & 63);
    int rgrp = tid >> 6;
    float acc[16];
#pragma unroll
    for (int i = 0; i < 16; i++) acc[i] = 0.f;
    __shared__ float As[64][33];
    __shared__ float Ws[32][65];
    for (int kc = 0; kc < Fc; kc += 32) {
        for (int e = tid; e < 64 * 32; e += 256) {
            int r = e >> 5, kk = e & 31;
            As[r][kk] = feat[(size_t)(rowbase + r) * Fc + kc + kk];
        }
        for (int e = tid; e < 32 * 64; e += 256) {
            int kk = e >> 6, c = e & 63;
            Ws[kk][c] = W2[(size_t)(kc + kk) * Hc + colbase + c];
        }
        __syncthreads();
#pragma unroll 8
        for (int kk = 0; kk < 32; kk++) {
            float w = Ws[kk][tid & 63];
#pragma unroll
            for (int i = 0; i < 16; i++) acc[i] += As[rgrp * 16 + i][kk] * w;
        }
        __syncthreads();
    }
    float bb = b2[col];
#pragma unroll
    for (int i = 0; i < 16; i++)
        g_encproj[(size_t)(rowbase + rgrp * 16 + i) * Hc + col] = acc[i] + bb;
}

// ---------------- persistent kernel ----------------
__global__ void __launch_bounds__(TPB, 1) k_persist(
    const float* __restrict__ feat, const float* __restrict__ emb,
    const float* __restrict__ W1, const float* __restrict__ b1,
    const float* __restrict__ Va, const float* __restrict__ bVa,
    const float* __restrict__ Wg, const float* __restrict__ bg,
    const float* __restrict__ Wx, const float* __restrict__ Whh,
    const float* __restrict__ blstm, const float* __restrict__ Wout,
    const float* __restrict__ bout, float* __restrict__ dout)
{
    const int bid = blockIdx.x;
    const int tid = threadIdx.x;
    __shared__ __align__(16) float sm[64 * 36];   // 9.2 KB
    __shared__ float sl[4096];                     // 16 KB
    __shared__ float sred[TPB];
    __shared__ int   sredi[TPB];
    __shared__ float s_aux[4];

    const int c127 = tid & 127;
    const int bg8 = (tid >> 7) * 8;   // 4 batch-groups of 8

    for (int t = 0; t < Tc; t++) {
        const int rp = t & 1, wp = rp ^ 1;

        // ========== P1: argmax(t-1)->x | hq/glin partials | gates h-part partials ==========
        if (bid < 16) {
            if (t > 0) {
                int half = tid >> 8;         // 0/1
                int lt = tid & 255;
                int b = bid * 2 + half;
                float bv = -INFINITY; int bi = 0x7fffffff;
                if (lt < NT79) {
                    bv = __ldcg(&g_pbv[lt * 32 + b]);
                    bi = __ldcg(&g_pbi[lt * 32 + b]);
                }
                sred[tid] = bv; sredi[tid] = bi;
                __syncthreads();
                for (int o = 128; o; o >>= 1) {
                    if (lt < o) {
                        if (sred[tid + o] > sred[tid] ||
                            (sred[tid + o] == sred[tid] && sredi[tid + o] < sredi[tid])) {
                            sred[tid] = sred[tid + o];
                            sredi[tid] = sredi[tid + o];
                        }
                    }
                    __syncthreads();
                }
                int best = sredi[half * 256];
                for (int e = lt; e < Ec; e += 256)
                    g_x[b * Ec + e] = emb[(size_t)best * Ec + e];
            }
        } else if (bid < 72) {
            // hq/glin: 14 tiles x 4 K-chunks(128). tiles 0-3 hq, 4-13 glin
            int u = bid - 16;
            int tile = u >> 2, kq = u & 3;
            int cg = tile * 128 + c127;
            const float* Wp; size_t ldw; float* dstp; int cloc;
            if (tile < 4) { Wp = W1 + cg; ldw = Hc; dstp = g_hqp[kq]; cloc = cg; }
            else { cloc = cg - 512; Wp = Wg + cloc; ldw = Fc; dstp = g_glp[kq]; }
            ull a0 = 0, a1 = 0, a2 = 0, a3 = 0;
            const float* hsrc = g_h[rp];
            int k0 = kq * 128;
            for (int kc = k0; kc < k0 + 128; kc += 64) {
                __syncthreads();
                stage_g(sm, hsrc, kc, Hc, tid);
                __syncthreads();
                gemm_chunk(Wp + (size_t)kc * ldw, ldw, sm, bg8, a0, a1, a2, a3);
            }
            float2 p0 = un2(a0), p1 = un2(a1), p2 = un2(a2), p3 = un2(a3);
            float vals[8] = {p0.x, p0.y, p1.x, p1.y, p2.x, p2.y, p3.x, p3.y};
            int stride = (tile < 4) ? Hc : Fc;
#pragma unroll
            for (int i = 0; i < 8; i++)
                dstp[(size_t)(bg8 + i) * stride + cloc] = vals[i];
        } else if (bid < 136) {
            // gates h-part: 16 tiles x 4 K-chunks(128) over Whh
            int u = bid - 72;
            int tile = u >> 2, kq = u & 3;
            int col = tile * 128 + c127;
            ull a0 = 0, a1 = 0, a2 = 0, a3 = 0;
            const float* hsrc = g_h[rp];
            int k0 = kq * 128;
            for (int kc = k0; kc < k0 + 128; kc += 64) {
                __syncthreads();
                stage_g(sm, hsrc, kc, Hc, tid);
                __syncthreads();
                gemm_chunk(Whh + (size_t)kc * G4 + col, G4, sm, bg8, a0, a1, a2, a3);
            }
            float2 p0 = un2(a0), p1 = un2(a1), p2 = un2(a2), p3 = un2(a3);
            float vals[8] = {p0.x, p0.y, p1.x, p1.y, p2.x, p2.y, p3.x, p3.y};
            float* gp = g_gp[kq];
#pragma unroll
            for (int i = 0; i < 8; i++)
                gp[(size_t)(bg8 + i) * G4 + col] = vals[i];
        }
        gridbar();

        // ========== P2: attention (4 blocks per batch) ==========
        if (bid < 128) {
            int b = bid >> 2, sub = bid & 3;
            {
                int k = tid;  // Hc == TPB
                float hv = b1[k];
#pragma unroll
                for (int q = 0; q < 4; q++) hv += __ldcg(&g_hqp[q][b * Hc + k]);
                sl[k] = hv;
            }
            __syncthreads();
            int warp = tid >> 5, lane = tid & 31;
#pragma unroll
            for (int ni = 0; ni < 4; ni++) {
                int n = warp + ni * 16;
                const float* ep = g_encproj + (size_t)(b * Nc + n) * Hc;
                float acc = 0.f;
#pragma unroll 4
                for (int k = lane; k < Hc; k += 32) {
                    float v = sl[k] + ep[k];
                    acc = fmaf(fmaxf(v, 0.f), Va[k], acc);
                }
#pragma unroll
                for (int o = 16; o; o >>= 1) acc += __shfl_down_sync(0xffffffffu, acc, o);
                if (lane == 0) sred[n] = acc + bVa[0];
            }
            __syncthreads();
            if (tid < 64) {
                float m = sred[tid];
#pragma unroll
                for (int o = 16; o; o >>= 1) m = fmaxf(m, __shfl_xor_sync(0xffffffffu, m, o));
                if (lane == 0) s_aux[tid >> 5] = m;
            }
            __syncthreads();
            if (tid < 64) {
                float M = fmaxf(s_aux[0], s_aux[1]);
                float e = expf(sred[tid] - M);
                sred[tid] = e;
                float ss = e;
#pragma unroll
                for (int o = 16; o; o >>= 1) ss += __shfl_xor_sync(0xffffffffu, ss, o);
                if (lane == 0) s_aux[2 + (tid >> 5)] = ss;
            }
            __syncthreads();
            if (tid < 64) {
                float wv = sred[tid] / (s_aux[2] + s_aux[3]);
                sred[tid] = wv;
                if (sub == 0)
                    dout[AOFF + (size_t)b * Tc * Nc + (size_t)t * Nc + tid] = wv;
            }
            __syncthreads();
            if (tid < 320) {
                int f = sub * 320 + tid;
                const float* fb = feat + (size_t)b * Nc * Fc + f;
                float acc = 0.f;
#pragma unroll 8
                for (int n = 0; n < 64; n++) acc = fmaf(fb[(size_t)n * Fc], sred[n], acc);
                float gl = bg[f];
#pragma unroll
                for (int q = 0; q < 4; q++) gl += __ldcg(&g_glp[q][b * Fc + f]);
                g_ctx[b * Fc + f] = acc * sigf(gl);
            }
        }
        gridbar();

        // ========== P3: gates x/ctx part: 16 tiles x 7 K-chunks(256) ==========
        if (bid < 112) {
            int tile = bid / 7, kch = bid % 7;
            int col = tile * 128 + c127;
            int kbase = kch * 256;
            ull a0 = 0, a1 = 0, a2 = 0, a3 = 0;
            for (int kc = kbase; kc < kbase + 256; kc += 64) {
                __syncthreads();
#pragma unroll
                for (int e = tid; e < 2048; e += TPB) {
                    int kk = e >> 5, b = e & 31;
                    int k = kc + kk;
                    sm[kk * 36 + b] = (k < Ec) ? __ldcg(&g_x[b * Ec + k])
                                               : __ldcg(&g_ctx[b * Fc + (k - Ec)]);
                }
                __syncthreads();
                gemm_chunk(Wx + (size_t)kc * G4 + col, G4, sm, bg8, a0, a1, a2, a3);
            }
            float2 p0 = un2(a0), p1 = un2(a1), p2 = un2(a2), p3 = un2(a3);
            float vals[8] = {p0.x, p0.y, p1.x, p1.y, p2.x, p2.y, p3.x, p3.y};
            float* gp = g_gp[4 + kch];
#pragma unroll
            for (int i = 0; i < 8; i++)
                gp[(size_t)(bg8 + i) * G4 + col] = vals[i];
        }
        gridbar();

        // ========== P3b: LSTM pointwise (reduce 11 partials) ==========
        if (bid < 32) {
            int id = bid * TPB + tid;          // 0..16383
            int b = id >> 9, j = id & 511;
            float gi = blstm[j], gf = blstm[Hc + j], gg = blstm[2 * Hc + j], go = blstm[3 * Hc + j];
#pragma unroll
            for (int p = 0; p < 11; p++) {
                const float* gp = g_gp[p] + (size_t)b * G4;
                gi += __ldcg(&gp[j]);
                gf += __ldcg(&gp[Hc + j]);
                gg += __ldcg(&gp[2 * Hc + j]);
                go += __ldcg(&gp[3 * Hc + j]);
            }
            float cprev = g_c[rp][b * Hc + j];
            float iv = sigf(gi), fv = sigf(gf), gv = tanhf(gg), ov = sigf(go);
            float c2 = fv * cprev + iv * gv;
            float h2 = ov * tanhf(c2);
            g_c[wp][b * Hc + j] = c2;
            g_h[wp][b * Hc + j] = h2;
            if (t == Tc - 1) {
                dout[HOFF + b * Hc + j] = h2;
                dout[COFF + b * Hc + j] = c2;
            }
        }
        gridbar();

        // ========== P4: logits partials: 79 tiles(128 col) x 2 K-halves ==========
        for (int u = bid; u < 158; u += NBLK) {
            int tile = u >> 1, kh = u & 1;
            int col = tile * 128 + c127;
            int colc = (col < Vc) ? col : (Vc - 1);
            ull a0 = 0, a1 = 0, a2 = 0, a3 = 0;
            const float* hsrc = g_h[wp];
            int k0 = kh * 256;
            for (int kc = k0; kc < k0 + 256; kc += 64) {
                __syncthreads();
                stage_g(sm, hsrc, kc, Hc, tid);
                __syncthreads();
                gemm_chunk(Wout + (size_t)kc * Vc + colc, Vc, sm, bg8, a0, a1, a2, a3);
            }
            float2 p0 = un2(a0), p1 = un2(a1), p2 = un2(a2), p3 = un2(a3);
            float vals[8] = {p0.x, p0.y, p1.x, p1.y, p2.x, p2.y, p3.x, p3.y};
            float* lp = g_lp[kh];
#pragma unroll
            for (int i = 0; i < 8; i++)
                lp[(size_t)(bg8 + i) * LPW + col] = vals[i];
            __syncthreads();
        }
        gridbar();

        // ========== P5: reduce + bias + store logits + per-tile argmax ==========
        if (bid < NT79) {
            int tile = bid;
            int col = tile * 128 + c127;
            bool valid = (col < Vc);
            float bo = valid ? bout[col] : 0.f;
#pragma unroll
            for (int i = 0; i < 8; i++) {
                int b = bg8 + i;
                float v = -INFINITY;
                if (valid) {
                    v = __ldcg(&g_lp[0][(size_t)b * LPW + col]) +
                        __ldcg(&g_lp[1][(size_t)b * LPW + col]) + bo;
                    dout[(size_t)b * Tc * Vc + (size_t)t * Vc + col] = v;
                }
                sl[b * 128 + c127] = v;
            }
            __syncthreads();
            if (tid < 32) {
                int b = tid;
                float bv = -INFINITY; int bi = 0;
#pragma unroll 8
                for (int cq = 0; cq < 128; cq++) {
                    float v = sl[b * 128 + cq];
                    if (v > bv) { bv = v; bi = tile * 128 + cq; }
                }
                g_pbv[tile * 32 + b] = bv;
                g_pbi[tile * 32 + b] = bi;
            }
        }
        gridbar();
    }
}

// ---------------- launcher ----------------
extern "C" void kernel_launch(void* const* d_in, const int* in_sizes, int n_in,
                              void* d_out, int out_size) {
    int off = (n_in > 2 && in_sizes[2] == 1) ? 1 : 0;
    const float* feat  = (const float*)d_in[0];
    const float* emb   = (const float*)d_in[2 + off];
    const float* W1    = (const float*)d_in[3 + off];
    const float* b1    = (const float*)d_in[4 + off];
    const float* W2    = (const float*)d_in[5 + off];
    const float* b2    = (const float*)d_in[6 + off];
    const float* Va    = (const float*)d_in[7 + off];
    const float* bVa   = (const float*)d_in[8 + off];
    const float* Wh    = (const float*)d_in[9 + off];
    const float* bh    = (const float*)d_in[10 + off];
    const float* Wc    = (const float*)d_in[11 + off];
    const float* bc    = (const float*)d_in[12 + off];
    const float* Wg    = (const float*)d_in[13 + off];
    const float* bg    = (const float*)d_in[14 + off];
    const float* Wx    = (const float*)d_in[15 + off];
    const float* Whh   = (const float*)d_in[16 + off];
    const float* blstm = (const float*)d_in[17 + off];
    const float* Wout  = (const float*)d_in[18 + off];
    const float* bout  = (const float*)d_in[19 + off];
    float* out = (float*)d_out;

    k_mean<<<160, 256>>>(feat, emb);
    k_h0c0<<<16, 256>>>(Wh, bh, Wc, bc);
    k_encproj<<<dim3(32, 8), 256>>>(feat, W2, b2);
    k_persist<<<NBLK, TPB>>>(feat, emb, W1, b1, Va, bVa, Wg, bg,
                             Wx, Whh, blstm, Wout, bout, out);
}

// round 7
// speedup vs baseline: 3.2035x; 1.0241x over previous
#include <cuda_runtime.h>
#include <cuda_bf16.h>
#include <math.h>

#define Bc 32
#define Nc 64
#define Fc 1280
#define Hc 512
#define Ec 512
#define Vc 10000
#define Tc 80
#define SOSc 1
#define G4 2048
#define NBLK 148
#define TPB 512
#define LPW 10112
#define NT79 79

typedef unsigned long long ull;

// ---------------- device scratch ----------------
__device__ float g_h[2][Bc * Hc];
__device__ float g_c[2][Bc * Hc];
__device__ float g_x[Bc * Ec];
__device__ float g_hqp[4][Bc * Hc];    // hq partials (K-split 4)
__device__ float g_glp[4][Bc * Fc];    // glin partials (K-split 4)
__device__ float g_ctx[Bc * Fc];
__device__ float g_encproj[Bc * Nc * Hc];
__device__ float g_mean[Bc * Fc];
__device__ float g_gp[18][Bc * G4];    // gates partials: 0..3 h-part, 4..17 x-part
__device__ float g_lp[4][Bc * LPW];    // logits partials (K-split 4)
__device__ float g_pbv[NT79 * Bc];
__device__ int   g_pbi[NT79 * Bc];
__device__ unsigned g_bar;

#define HOFF ((size_t)Bc * Tc * Vc)
#define COFF (HOFF + (size_t)Bc * Hc)
#define AOFF (COFF + (size_t)Bc * Hc)

__device__ __forceinline__ float sigf(float x) { return 1.0f / (1.0f + expf(-x)); }

// packed f32x2 helpers
__device__ __forceinline__ ull pk2(float x) {
    ull r; asm("mov.b64 %0,{%1,%1};" : "=l"(r) : "r"(__float_as_uint(x))); return r;
}
__device__ __forceinline__ void fma2(ull& d, ull a, ull b) {
    asm("fma.rn.f32x2 %0,%1,%2,%0;" : "+l"(d) : "l"(a), "l"(b));
}
__device__ __forceinline__ float2 un2(ull v) {
    unsigned lo, hi; asm("mov.b64 {%0,%1},%2;" : "=r"(lo), "=r"(hi) : "l"(v));
    float2 f; f.x = __uint_as_float(lo); f.y = __uint_as_float(hi); return f;
}

__device__ __forceinline__ void gridbar() {
    __syncthreads();
    if (threadIdx.x == 0) {
        __threadfence();
        unsigned t = atomicAdd(&g_bar, 1u) + 1u;
        unsigned target = ((t + NBLK - 1u) / NBLK) * NBLK;
        while (*((volatile unsigned*)&g_bar) < target) __nanosleep(64);
        __threadfence();
    }
    __syncthreads();
}

// stage NKK k-values x 32 batches, transposed: sm[kk*36 + b]
template <int NKK>
__device__ __forceinline__ void stage_h(float* sm, const float* __restrict__ src,
                                        int kc, int stride, int tid) {
#pragma unroll
    for (int e = tid; e < NKK * 32; e += TPB) {
        int kk = e >> 5, b = e & 31;
        sm[kk * 36 + b] = __ldcg(&src[b * stride + kc + kk]);
    }
}

// GEMM micro-tile: 4 adjacent cols x 2 batches per thread.
// Wp points at W[kc*ldw + c0] (c0 multiple of 4 => 16B aligned).
// Weights read as ulonglong2 (LDG.128, zero packing movs).
// a0=(c0,c1|b0) a1=(c2,c3|b0) a2=(c0,c1|b1) a3=(c2,c3|b1)
template <int NKK>
__device__ __forceinline__ void gemm4(const float* __restrict__ Wp, size_t ldw,
                                      const float* sm, int b2,
                                      ull& a0, ull& a1, ull& a2, ull& a3) {
    for (int kk8 = 0; kk8 < NKK; kk8 += 8) {
        ulonglong2 wv[8];
#pragma unroll
        for (int u = 0; u < 8; u++)
            wv[u] = *(const ulonglong2*)(Wp + (size_t)(kk8 + u) * ldw);
#pragma unroll
        for (int u = 0; u < 8; u++) {
            float2 bb = *(const float2*)&sm[(kk8 + u) * 36 + b2];
            ull p0 = pk2(bb.x), p1 = pk2(bb.y);
            fma2(a0, wv[u].x, p0); fma2(a1, wv[u].y, p0);
            fma2(a2, wv[u].x, p1); fma2(a3, wv[u].y, p1);
        }
    }
}

// ---------------- init kernels ----------------
__global__ void k_mean(const float* __restrict__ feat, const float* __restrict__ emb) {
    int idx = blockIdx.x * blockDim.x + threadIdx.x;
    if (idx == 0) g_bar = 0u;
    if (idx < Bc * Ec) g_x[idx] = emb[(size_t)SOSc * Ec + (idx % Ec)];
    if (idx >= Bc * Fc) return;
    int b = idx / Fc, f = idx % Fc;
    float s = 0.f;
    const float* p = feat + (size_t)b * Nc * Fc + f;
#pragma unroll 8
    for (int n = 0; n < Nc; n++) s += p[(size_t)n * Fc];
    g_mean[idx] = s * (1.0f / 64.0f);
}

__global__ void k_h0c0(const float* __restrict__ Wh, const float* __restrict__ bh,
                       const float* __restrict__ Wc, const float* __restrict__ bc) {
    __shared__ __align__(16) float sm[64 * 36];
    int tid = threadIdx.x;
    int colg = blockIdx.x * 64 + (tid & 63);
    int bgrp = tid >> 6;
    float acc[8] = {0, 0, 0, 0, 0, 0, 0, 0};
    const float* W; float bias; float* dst;
    if (colg < Hc) { W = Wh + colg; bias = bh[colg]; dst = g_h[0] + colg; }
    else { W = Wc + (colg - Hc); bias = bc[colg - Hc]; dst = g_c[0] + (colg - Hc); }
    for (int kc = 0; kc < Fc; kc += 64) {
        __syncthreads();
        for (int e = tid; e < 2048; e += 256) {
            int kk = e >> 5, b = e & 31;
            sm[kk * 36 + b] = g_mean[b * Fc + kc + kk];
        }
        __syncthreads();
#pragma unroll 8
        for (int kk = 0; kk < 64; kk++) {
            float w = W[(size_t)(kc + kk) * Hc];
            const float* xr = &sm[kk * 36 + bgrp * 8];
#pragma unroll
            for (int i = 0; i < 8; i++) acc[i] = fmaf(xr[i], w, acc[i]);
        }
    }
#pragma unroll
    for (int i = 0; i < 8; i++) dst[(bgrp * 8 + i) * Hc] = acc[i] + bias;
}

__global__ void k_encproj(const float* __restrict__ feat, const float* __restrict__ W2,
                          const float* __restrict__ b2) {
    int tid = threadIdx.x;
    int rowbase = blockIdx.x * 64;
    int colbase = blockIdx.y * 64;
    int col = colbase + (tid & 63);
    int rgrp = tid >> 6;
    float acc[16];
#pragma unroll
    for (int i = 0; i < 16; i++) acc[i] = 0.f;
    __shared__ float As[64][33];
    __shared__ float Ws[32][65];
    for (int kc = 0; kc < Fc; kc += 32) {
        for (int e = tid; e < 64 * 32; e += 256) {
            int r = e >> 5, kk = e & 31;
            As[r][kk] = feat[(size_t)(rowbase + r) * Fc + kc + kk];
        }
        for (int e = tid; e < 32 * 64; e += 256) {
            int kk = e >> 6, c = e & 63;
            Ws[kk][c] = W2[(size_t)(kc + kk) * Hc + colbase + c];
        }
        __syncthreads();
#pragma unroll 8
        for (int kk = 0; kk < 32; kk++) {
            float w = Ws[kk][tid & 63];
#pragma unroll
            for (int i = 0; i < 16; i++) acc[i] += As[rgrp * 16 + i][kk] * w;
        }
        __syncthreads();
    }
    float bb = b2[col];
#pragma unroll
    for (int i = 0; i < 16; i++)
        g_encproj[(size_t)(rowbase + rgrp * 16 + i) * Hc + col] = acc[i] + bb;
}

// ---------------- persistent kernel ----------------
__global__ void __launch_bounds__(TPB, 1) k_persist(
    const float* __restrict__ feat, const float* __restrict__ emb,
    const float* __restrict__ W1, const float* __restrict__ b1,
    const float* __restrict__ Va, const float* __restrict__ bVa,
    const float* __restrict__ Wg, const float* __restrict__ bg,
    const float* __restrict__ Wx, const float* __restrict__ Whh,
    const float* __restrict__ blstm, const float* __restrict__ Wout,
    const float* __restrict__ bout, float* __restrict__ dout)
{
    const int bid = blockIdx.x;
    const int tid = threadIdx.x;
    __shared__ __align__(16) float sm[128 * 36];   // 18.4 KB staged k-tile
    __shared__ float sl[4096];                      // 16 KB
    __shared__ float sred[TPB];
    __shared__ int   sredi[TPB];
    __shared__ float s_aux[4];

    const int ct = tid & 31;           // col-thread (32 per tile of 128 cols)
    const int c4 = ct * 4;             // local col base (4 adjacent cols)
    const int b2 = (tid >> 5) * 2;     // batch pair base (16 groups of 2)

    for (int t = 0; t < Tc; t++) {
        const int rp = t & 1, wp = rp ^ 1;

        // ===== P1: argmax(t-1)->x | hq/glin partials | gates h-part partials =====
        if (bid < 16) {
            if (t > 0) {
                int half = tid >> 8, lt = tid & 255;
                int b = bid * 2 + half;
                float bv = -INFINITY; int bi = 0x7fffffff;
                if (lt < NT79) {
                    bv = __ldcg(&g_pbv[lt * 32 + b]);
                    bi = __ldcg(&g_pbi[lt * 32 + b]);
                }
                sred[tid] = bv; sredi[tid] = bi;
                __syncthreads();
                for (int o = 128; o; o >>= 1) {
                    if (lt < o) {
                        if (sred[tid + o] > sred[tid] ||
                            (sred[tid + o] == sred[tid] && sredi[tid + o] < sredi[tid])) {
                            sred[tid] = sred[tid + o];
                            sredi[tid] = sredi[tid + o];
                        }
                    }
                    __syncthreads();
                }
                int best = sredi[half * 256];
                for (int e = lt; e < Ec; e += 256)
                    g_x[b * Ec + e] = emb[(size_t)best * Ec + e];
            }
        } else if (bid < 72) {
            // hq (tiles 0-3) / glin (tiles 4-13): 14 tiles(128c) x 4 K-chunks(128)
            int u = bid - 16;
            int tile = u >> 2, kq = u & 3;
            int cg = tile * 128 + c4;
            const float* Wp; size_t ldw; float* dstp; int cloc;
            if (tile < 4) { Wp = W1; ldw = Hc; dstp = g_hqp[kq]; cloc = cg; }
            else { cloc = cg - 512; Wp = Wg; ldw = Fc; dstp = g_glp[kq]; }
            ull a0 = 0, a1 = 0, a2 = 0, a3 = 0;
            int kc = kq * 128;
            stage_h<128>(sm, g_h[rp], kc, Hc, tid);
            __syncthreads();
            gemm4<128>(Wp + (size_t)kc * ldw + cloc, ldw, sm, b2, a0, a1, a2, a3);
            float2 q0 = un2(a0), q1 = un2(a1), q2 = un2(a2), q3 = un2(a3);
            *(float4*)&dstp[(size_t)(b2 + 0) * ldw + cloc] = make_float4(q0.x, q0.y, q1.x, q1.y);
            *(float4*)&dstp[(size_t)(b2 + 1) * ldw + cloc] = make_float4(q2.x, q2.y, q3.x, q3.y);
        } else if (bid < 136) {
            // gates h-part: 16 tiles(128c) x 4 K-chunks(128) over Whh
            int u = bid - 72;
            int tile = u >> 2, kq = u & 3;
            int col = tile * 128 + c4;
            ull a0 = 0, a1 = 0, a2 = 0, a3 = 0;
            int kc = kq * 128;
            stage_h<128>(sm, g_h[rp], kc, Hc, tid);
            __syncthreads();
            gemm4<128>(Whh + (size_t)kc * G4 + col, G4, sm, b2, a0, a1, a2, a3);
            float2 q0 = un2(a0), q1 = un2(a1), q2 = un2(a2), q3 = un2(a3);
            float* gp = g_gp[kq];
            *(float4*)&gp[(size_t)(b2 + 0) * G4 + col] = make_float4(q0.x, q0.y, q1.x, q1.y);
            *(float4*)&gp[(size_t)(b2 + 1) * G4 + col] = make_float4(q2.x, q2.y, q3.x, q3.y);
        }
        gridbar();

        // ===== P2: attention (4 blocks per batch) =====
        if (bid < 128) {
            int b = bid >> 2, sub = bid & 3;
            {
                int k = tid;  // Hc == TPB
                float hv = b1[k];
#pragma unroll
                for (int q = 0; q < 4; q++) hv += __ldcg(&g_hqp[q][b * Hc + k]);
                sl[k] = hv;
            }
            __syncthreads();
            int warp = tid >> 5, lane = tid & 31;
#pragma unroll
            for (int ni = 0; ni < 4; ni++) {
                int n = warp + ni * 16;
                const float* ep = g_encproj + (size_t)(b * Nc + n) * Hc;
                float acc = 0.f;
#pragma unroll 4
                for (int k = lane; k < Hc; k += 32) {
                    float v = sl[k] + ep[k];
                    acc = fmaf(fmaxf(v, 0.f), Va[k], acc);
                }
#pragma unroll
                for (int o = 16; o; o >>= 1) acc += __shfl_down_sync(0xffffffffu, acc, o);
                if (lane == 0) sred[n] = acc + bVa[0];
            }
            __syncthreads();
            if (tid < 64) {
                float m = sred[tid];
#pragma unroll
                for (int o = 16; o; o >>= 1) m = fmaxf(m, __shfl_xor_sync(0xffffffffu, m, o));
                if (lane == 0) s_aux[tid >> 5] = m;
            }
            __syncthreads();
            if (tid < 64) {
                float M = fmaxf(s_aux[0], s_aux[1]);
                float e = expf(sred[tid] - M);
                sred[tid] = e;
                float ss = e;
#pragma unroll
                for (int o = 16; o; o >>= 1) ss += __shfl_xor_sync(0xffffffffu, ss, o);
                if (lane == 0) s_aux[2 + (tid >> 5)] = ss;
            }
            __syncthreads();
            if (tid < 64) {
                float wv = sred[tid] / (s_aux[2] + s_aux[3]);
                sred[tid] = wv;
                if (sub == 0)
                    dout[AOFF + (size_t)b * Tc * Nc + (size_t)t * Nc + tid] = wv;
            }
            __syncthreads();
            if (tid < 320) {
                int f = sub * 320 + tid;
                const float* fb = feat + (size_t)b * Nc * Fc + f;
                float acc = 0.f;
#pragma unroll 8
                for (int n = 0; n < 64; n++) acc = fmaf(fb[(size_t)n * Fc], sred[n], acc);
                float gl = bg[f];
#pragma unroll
                for (int q = 0; q < 4; q++) gl += __ldcg(&g_glp[q][b * Fc + f]);
                g_ctx[b * Fc + f] = acc * sigf(gl);
            }
        }
        gridbar();

        // ===== P3: gates x/ctx part: 16 tiles(128c) x 14 K-chunks(128) = 224 units =====
        for (int u = bid; u < 224; u += NBLK) {
            int tile = u / 14, kch = u % 14;
            int col = tile * 128 + c4;
            int kbase = kch * 128;
            ull a0 = 0, a1 = 0, a2 = 0, a3 = 0;
            __syncthreads();
#pragma unroll
            for (int e = tid; e < 4096; e += TPB) {
                int kk = e >> 5, b = e & 31;
                int k = kbase + kk;
                sm[kk * 36 + b] = (k < Ec) ? __ldcg(&g_x[b * Ec + k])
                                           : __ldcg(&g_ctx[b * Fc + (k - Ec)]);
            }
            __syncthreads();
            gemm4<128>(Wx + (size_t)kbase * G4 + col, G4, sm, b2, a0, a1, a2, a3);
            float2 q0 = un2(a0), q1 = un2(a1), q2 = un2(a2), q3 = un2(a3);
            float* gp = g_gp[4 + kch];
            *(float4*)&gp[(size_t)(b2 + 0) * G4 + col] = make_float4(q0.x, q0.y, q1.x, q1.y);
            *(float4*)&gp[(size_t)(b2 + 1) * G4 + col] = make_float4(q2.x, q2.y, q3.x, q3.y);
        }
        gridbar();

        // ===== P3b: LSTM pointwise (reduce 18 partials) =====
        if (bid < 32) {
            int id = bid * TPB + tid;          // 0..16383
            int b = id >> 9, j = id & 511;
            float gi = blstm[j], gf = blstm[Hc + j], gg = blstm[2 * Hc + j], go = blstm[3 * Hc + j];
#pragma unroll
            for (int p = 0; p < 18; p++) {
                const float* gp = g_gp[p] + (size_t)b * G4;
                gi += __ldcg(&gp[j]);
                gf += __ldcg(&gp[Hc + j]);
                gg += __ldcg(&gp[2 * Hc + j]);
                go += __ldcg(&gp[3 * Hc + j]);
            }
            float cprev = g_c[rp][b * Hc + j];
            float iv = sigf(gi), fv = sigf(gf), gv = tanhf(gg), ov = sigf(go);
            float c2 = fv * cprev + iv * gv;
            float h2 = ov * tanhf(c2);
            g_c[wp][b * Hc + j] = c2;
            g_h[wp][b * Hc + j] = h2;
            if (t == Tc - 1) {
                dout[HOFF + b * Hc + j] = h2;
                dout[COFF + b * Hc + j] = c2;
            }
        }
        gridbar();

        // ===== P4: logits partials: 79 tiles(128c) x 4 K-chunks(128) = 316 units =====
        for (int u = bid; u < 316; u += NBLK) {
            int tile = u >> 2, kq = u & 3;
            int col = tile * 128 + c4;
            int colc = (col <= Vc - 4) ? col : (Vc - 4);   // aligned clamp for OOB cols
            ull a0 = 0, a1 = 0, a2 = 0, a3 = 0;
            int kc = kq * 128;
            __syncthreads();
            stage_h<128>(sm, g_h[wp], kc, Hc, tid);
            __syncthreads();
            gemm4<128>(Wout + (size_t)kc * Vc + colc, Vc, sm, b2, a0, a1, a2, a3);
            float2 q0 = un2(a0), q1 = un2(a1), q2 = un2(a2), q3 = un2(a3);
            float* lp = g_lp[kq];
            *(float4*)&lp[(size_t)(b2 + 0) * LPW + col] = make_float4(q0.x, q0.y, q1.x, q1.y);
            *(float4*)&lp[(size_t)(b2 + 1) * LPW + col] = make_float4(q2.x, q2.y, q3.x, q3.y);
        }
        gridbar();

        // ===== P5: reduce 4 partials + bias + store logits + per-tile argmax =====
        if (bid < NT79) {
            int tile = bid;
            int col0 = tile * 128 + c4;
#pragma unroll
            for (int bb = 0; bb < 2; bb++) {
                int b = b2 + bb;
#pragma unroll
                for (int j = 0; j < 4; j++) {
                    int col = col0 + j;
                    bool valid = (col < Vc);
                    float v = -INFINITY;
                    if (valid) {
                        v = bout[col];
#pragma unroll
                        for (int q = 0; q < 4; q++)
                            v += __ldcg(&g_lp[q][(size_t)b * LPW + col]);
                        dout[(size_t)b * Tc * Vc + (size_t)t * Vc + col] = v;
                    }
                    sl[b * 128 + c4 + j] = v;
                }
            }
            __syncthreads();
            if (tid < 32) {
                int b = tid;
                float bv = -INFINITY; int bi = 0;
#pragma unroll 8
                for (int cq = 0; cq < 128; cq++) {
                    float v = sl[b * 128 + cq];
                    if (v > bv) { bv = v; bi = tile * 128 + cq; }
                }
                g_pbv[tile * 32 + b] = bv;
                g_pbi[tile * 32 + b] = bi;
            }
        }
        gridbar();
    }
}

// ---------------- launcher ----------------
extern "C" void kernel_launch(void* const* d_in, const int* in_sizes, int n_in,
                              void* d_out, int out_size) {
    int off = (n_in > 2 && in_sizes[2] == 1) ? 1 : 0;
    const float* feat  = (const float*)d_in[0];
    const float* emb   = (const float*)d_in[2 + off];
    const float* W1    = (const float*)d_in[3 + off];
    const float* b1    = (const float*)d_in[4 + off];
    const float* W2    = (const float*)d_in[5 + off];
    const float* b2    = (const float*)d_in[6 + off];
    const float* Va    = (const float*)d_in[7 + off];
    const float* bVa   = (const float*)d_in[8 + off];
    const float* Wh    = (const float*)d_in[9 + off];
    const float* bh    = (const float*)d_in[10 + off];
    const float* Wc    = (const float*)d_in[11 + off];
    const float* bc    = (const float*)d_in[12 + off];
    const float* Wg    = (const float*)d_in[13 + off];
    const float* bg    = (const float*)d_in[14 + off];
    const float* Wx    = (const float*)d_in[15 + off];
    const float* Whh   = (const float*)d_in[16 + off];
    const float* blstm = (const float*)d_in[17 + off];
    const float* Wout  = (const float*)d_in[18 + off];
    const float* bout  = (const float*)d_in[19 + off];
    float* out = (float*)d_out;

    k_mean<<<160, 256>>>(feat, emb);
    k_h0c0<<<16, 256>>>(Wh, bh, Wc, bc);
    k_encproj<<<dim3(32, 8), 256>>>(feat, W2, b2);
    k_persist<<<NBLK, TPB>>>(feat, emb, W1, b1, Va, bVa, Wg, bg,
                             Wx, Whh, blstm, Wout, bout, out);
}

// round 8
// speedup vs baseline: 4.4239x; 1.3810x over previous
#include <cuda_runtime.h>
#include <cuda_bf16.h>
#include <math.h>

#define Bc 32
#define Nc 64
#define Fc 1280
#define Hc 512
#define Ec 512
#define Vc 10000
#define Tc 80
#define SOSc 1
#define G4 2048
#define NBLK 148
#define TPB 512
#define LPW 10112
#define NT79 79

typedef unsigned long long ull;

// ---------------- device scratch ----------------
__device__ float g_h[2][Bc * Hc];
__device__ float g_c[2][Bc * Hc];
__device__ float g_x[Bc * Ec];
__device__ float g_hqp[4][Bc * Hc];    // hq partials (K-split 4)
__device__ float g_glp[4][Bc * Fc];    // glin partials (K-split 4)
__device__ float g_ctx[Bc * Fc];
__device__ float g_encproj[Bc * Nc * Hc];
__device__ float g_mean[Bc * Fc];
__device__ float g_gp[18][Bc * G4];    // gates partials: 0..3 h-part, 4..17 x-part
__device__ float g_lp[8][Bc * LPW];    // logits partials (K-split 8)
__device__ float g_pbv[NT79 * Bc];
__device__ int   g_pbi[NT79 * Bc];
__device__ unsigned g_bar;

#define HOFF ((size_t)Bc * Tc * Vc)
#define COFF (HOFF + (size_t)Bc * Hc)
#define AOFF (COFF + (size_t)Bc * Hc)

// dynamic smem carve (floats): sw 16384 | sb 4608 | sl 4096 | sred 512 | sredi 512 | aux 8
#define SMEM_FLOATS (16384 + 4608 + 4096 + 512 + 512 + 8)
#define SMEM_BYTES (SMEM_FLOATS * 4)

__device__ __forceinline__ float sigf(float x) { return 1.0f / (1.0f + expf(-x)); }

__device__ __forceinline__ ull pk2(float x) {
    ull r; asm("mov.b64 %0,{%1,%1};" : "=l"(r) : "r"(__float_as_uint(x))); return r;
}
__device__ __forceinline__ void fma2(ull& d, ull a, ull b) {
    asm("fma.rn.f32x2 %0,%1,%2,%0;" : "+l"(d) : "l"(a), "l"(b));
}
__device__ __forceinline__ ull add2(ull a, ull b) {
    ull d; asm("add.rn.f32x2 %0,%1,%2;" : "=l"(d) : "l"(a), "l"(b)); return d;
}
__device__ __forceinline__ float2 un2(ull v) {
    unsigned lo, hi; asm("mov.b64 {%0,%1},%2;" : "=r"(lo), "=r"(hi) : "l"(v));
    float2 f; f.x = __uint_as_float(lo); f.y = __uint_as_float(hi); return f;
}

__device__ __forceinline__ void gridbar() {
    __syncthreads();
    if (threadIdx.x == 0) {
        __threadfence();
        unsigned t = atomicAdd(&g_bar, 1u) + 1u;
        unsigned target = ((t + NBLK - 1u) / NBLK) * NBLK;
        while (*((volatile unsigned*)&g_bar) < target) __nanosleep(64);
        __threadfence();
    }
    __syncthreads();
}

// ================= unified SMEM-tile GEMM unit =================
// Computes partial C[32 x 128cols] += op[32 x NKK] @ W[NKK x 128cols] and stores
// to dstp[(b)*dst_stride + c]. Weights staged ONCE into sw; operand transposed
// into sb[kk*36+b]. Two kk-planes (tid>>8) reduced in-block via add.rn.f32x2.
// SRCMODE 0: operand = src[b*sstride + k]. SRCMODE 1: x/ctx concat.
template <int NKK, int SRCMODE>
__device__ __forceinline__ void unit_gemm(
    float* sw, float* sb,
    const float* __restrict__ W, size_t ldw, int kc, int col0, int maxc,
    const float* __restrict__ src, int sstride,
    float* dstp, size_t dst_stride, int tid)
{
    // stage weights: NKK rows x 128 cols, coalesced LDG.128 rows
    {
        int maxc4 = maxc - 4;
#pragma unroll
        for (int e = tid; e < NKK * 32; e += TPB) {
            int kk = e >> 5, cc = (e & 31) << 2;
            int cg = col0 + cc; if (cg > maxc4) cg = maxc4;
            *(float4*)&sw[kk * 128 + cc] =
                *(const float4*)&W[(size_t)(kc + kk) * ldw + cg];
        }
    }
    // stage operand transposed: warp reads 32 consecutive k of one batch row
    {
        int warp = tid >> 5, lane = tid & 31;
#pragma unroll
        for (int idx = warp; idx < NKK; idx += 16) {
            int b = idx & 31, kkc = (idx >> 5) << 5;
            int k = kc + kkc + lane;
            float v;
            if (SRCMODE == 0) v = __ldcg(&src[b * sstride + k]);
            else v = (k < Ec) ? __ldcg(&g_x[b * Ec + k])
                              : __ldcg(&g_ctx[b * Fc + (k - Ec)]);
            sb[(kkc + lane) * 36 + b] = v;
        }
    }
    __syncthreads();
    int ks = tid >> 8, lt = tid & 255;
    int ct = lt & 31, bg = lt >> 5;
    int c4 = ct << 2, b4 = bg << 2;
    ull a0 = 0, a1 = 0, a2 = 0, a3 = 0, a4 = 0, a5 = 0, a6 = 0, a7 = 0;
    {
        const float* swp = sw + ks * (NKK / 2) * 128 + c4;
        const float* sbp = sb + ks * (NKK / 2) * 36 + b4;
#pragma unroll 4
        for (int kk = 0; kk < NKK / 2; kk++) {
            ulonglong2 w = *(const ulonglong2*)(swp + kk * 128);
            float4 bb = *(const float4*)(sbp + kk * 36);
            ull p0 = pk2(bb.x), p1 = pk2(bb.y), p2 = pk2(bb.z), p3 = pk2(bb.w);
            fma2(a0, w.x, p0); fma2(a1, w.y, p0);
            fma2(a2, w.x, p1); fma2(a3, w.y, p1);
            fma2(a4, w.x, p2); fma2(a5, w.y, p2);
            fma2(a6, w.x, p3); fma2(a7, w.y, p3);
        }
    }
    __syncthreads();
    ull* red = (ull*)sw;
    if (ks == 1) {
        red[lt * 8 + 0] = a0; red[lt * 8 + 1] = a1;
        red[lt * 8 + 2] = a2; red[lt * 8 + 3] = a3;
        red[lt * 8 + 4] = a4; red[lt * 8 + 5] = a5;
        red[lt * 8 + 6] = a6; red[lt * 8 + 7] = a7;
    }
    __syncthreads();
    if (ks == 0) {
        a0 = add2(a0, red[lt * 8 + 0]); a1 = add2(a1, red[lt * 8 + 1]);
        a2 = add2(a2, red[lt * 8 + 2]); a3 = add2(a3, red[lt * 8 + 3]);
        a4 = add2(a4, red[lt * 8 + 4]); a5 = add2(a5, red[lt * 8 + 5]);
        a6 = add2(a6, red[lt * 8 + 6]); a7 = add2(a7, red[lt * 8 + 7]);
        float2 q0, q1;
        q0 = un2(a0); q1 = un2(a1);
        *(float4*)&dstp[(size_t)(b4 + 0) * dst_stride + c4] = make_float4(q0.x, q0.y, q1.x, q1.y);
        q0 = un2(a2); q1 = un2(a3);
        *(float4*)&dstp[(size_t)(b4 + 1) * dst_stride + c4] = make_float4(q0.x, q0.y, q1.x, q1.y);
        q0 = un2(a4); q1 = un2(a5);
        *(float4*)&dstp[(size_t)(b4 + 2) * dst_stride + c4] = make_float4(q0.x, q0.y, q1.x, q1.y);
        q0 = un2(a6); q1 = un2(a7);
        *(float4*)&dstp[(size_t)(b4 + 3) * dst_stride + c4] = make_float4(q0.x, q0.y, q1.x, q1.y);
    }
    __syncthreads();
}

// ---------------- init kernels ----------------
__global__ void k_mean(const float* __restrict__ feat, const float* __restrict__ emb) {
    int idx = blockIdx.x * blockDim.x + threadIdx.x;
    if (idx == 0) g_bar = 0u;
    if (idx < Bc * Ec) g_x[idx] = emb[(size_t)SOSc * Ec + (idx % Ec)];
    if (idx >= Bc * Fc) return;
    int b = idx / Fc, f = idx % Fc;
    float s = 0.f;
    const float* p = feat + (size_t)b * Nc * Fc + f;
#pragma unroll 8
    for (int n = 0; n < Nc; n++) s += p[(size_t)n * Fc];
    g_mean[idx] = s * (1.0f / 64.0f);
}

__global__ void k_h0c0(const float* __restrict__ Wh, const float* __restrict__ bh,
                       const float* __restrict__ Wc, const float* __restrict__ bc) {
    __shared__ __align__(16) float sm[64 * 36];
    int tid = threadIdx.x;
    int colg = blockIdx.x * 64 + (tid & 63);
    int bgrp = tid >> 6;
    float acc[8] = {0, 0, 0, 0, 0, 0, 0, 0};
    const float* W; float bias; float* dst;
    if (colg < Hc) { W = Wh + colg; bias = bh[colg]; dst = g_h[0] + colg; }
    else { W = Wc + (colg - Hc); bias = bc[colg - Hc]; dst = g_c[0] + (colg - Hc); }
    for (int kc = 0; kc < Fc; kc += 64) {
        __syncthreads();
        for (int e = tid; e < 2048; e += 256) {
            int kk = e >> 5, b = e & 31;
            sm[kk * 36 + b] = g_mean[b * Fc + kc + kk];
        }
        __syncthreads();
#pragma unroll 8
        for (int kk = 0; kk < 64; kk++) {
            float w = W[(size_t)(kc + kk) * Hc];
            const float* xr = &sm[kk * 36 + bgrp * 8];
#pragma unroll
            for (int i = 0; i < 8; i++) acc[i] = fmaf(xr[i], w, acc[i]);
        }
    }
#pragma unroll
    for (int i = 0; i < 8; i++) dst[(bgrp * 8 + i) * Hc] = acc[i] + bias;
}

__global__ void k_encproj(const float* __restrict__ feat, const float* __restrict__ W2,
                          const float* __restrict__ b2) {
    int tid = threadIdx.x;
    int rowbase = blockIdx.x * 64;
    int colbase = blockIdx.y * 64;
    int col = colbase + (tid & 63);
    int rgrp = tid >> 6;
    float acc[16];
#pragma unroll
    for (int i = 0; i < 16; i++) acc[i] = 0.f;
    __shared__ float As[64][33];
    __shared__ float Ws[32][65];
    for (int kc = 0; kc < Fc; kc += 32) {
        for (int e = tid; e < 64 * 32; e += 256) {
            int r = e >> 5, kk = e & 31;
            As[r][kk] = feat[(size_t)(rowbase + r) * Fc + kc + kk];
        }
        for (int e = tid; e < 32 * 64; e += 256) {
            int kk = e >> 6, c = e & 63;
            Ws[kk][c] = W2[(size_t)(kc + kk) * Hc + colbase + c];
        }
        __syncthreads();
#pragma unroll 8
        for (int kk = 0; kk < 32; kk++) {
            float w = Ws[kk][tid & 63];
#pragma unroll
            for (int i = 0; i < 16; i++) acc[i] += As[rgrp * 16 + i][kk] * w;
        }
        __syncthreads();
    }
    float bb = b2[col];
#pragma unroll
    for (int i = 0; i < 16; i++)
        g_encproj[(size_t)(rowbase + rgrp * 16 + i) * Hc + col] = acc[i] + bb;
}

// ---------------- persistent kernel ----------------
__global__ void __launch_bounds__(TPB, 1) k_persist(
    const float* __restrict__ feat, const float* __restrict__ emb,
    const float* __restrict__ W1, const float* __restrict__ b1,
    const float* __restrict__ Va, const float* __restrict__ bVa,
    const float* __restrict__ Wg, const float* __restrict__ bg,
    const float* __restrict__ Wx, const float* __restrict__ Whh,
    const float* __restrict__ blstm, const float* __restrict__ Wout,
    const float* __restrict__ bout, float* __restrict__ dout)
{
    extern __shared__ __align__(16) float dsm[];
    float* sw   = dsm;                    // 16384 floats (64KB)
    float* sb   = dsm + 16384;            // 4608 floats
    float* sl   = sb + 4608;              // 4096 floats
    float* sred = sl + 4096;              // 512
    int*  sredi = (int*)(sred + 512);     // 512
    float* s_aux = (float*)(sredi + 512); // 8

    const int bid = blockIdx.x;
    const int tid = threadIdx.x;

    for (int t = 0; t < Tc; t++) {
        const int rp = t & 1, wp = rp ^ 1;

        // ===== P1: argmax(t-1)->x | hq/glin partials | gates h-part partials =====
        if (bid < 16) {
            if (t > 0) {
                int half = tid >> 8, lt = tid & 255;
                int b = bid * 2 + half;
                float bv = -INFINITY; int bi = 0x7fffffff;
                if (lt < NT79) {
                    bv = __ldcg(&g_pbv[lt * 32 + b]);
                    bi = __ldcg(&g_pbi[lt * 32 + b]);
                }
                sred[tid] = bv; sredi[tid] = bi;
                __syncthreads();
                for (int o = 128; o; o >>= 1) {
                    if (lt < o) {
                        if (sred[tid + o] > sred[tid] ||
                            (sred[tid + o] == sred[tid] && sredi[tid + o] < sredi[tid])) {
                            sred[tid] = sred[tid + o];
                            sredi[tid] = sredi[tid + o];
                        }
                    }
                    __syncthreads();
                }
                int best = sredi[half * 256];
                for (int e = lt; e < Ec; e += 256)
                    g_x[b * Ec + e] = emb[(size_t)best * Ec + e];
            }
        } else if (bid < 72) {
            int u = bid - 16, tile = u >> 2, kq = u & 3;
            int col0 = tile * 128, kc = kq * 128;
            if (tile < 4)
                unit_gemm<128, 0>(sw, sb, W1, Hc, kc, col0, Hc,
                                  g_h[rp], Hc, g_hqp[kq] + col0, Hc, tid);
            else
                unit_gemm<128, 0>(sw, sb, Wg, Fc, kc, col0 - 512, Fc,
                                  g_h[rp], Hc, g_glp[kq] + (col0 - 512), Fc, tid);
        } else if (bid < 136) {
            int u = bid - 72, tile = u >> 2, kq = u & 3;
            unit_gemm<128, 0>(sw, sb, Whh, G4, kq * 128, tile * 128, G4,
                              g_h[rp], Hc, g_gp[kq] + tile * 128, G4, tid);
        }
        gridbar();

        // ===== P2: attention (4 blocks per batch) =====
        if (bid < 128) {
            int b = bid >> 2, sub = bid & 3;
            {
                int k = tid;  // Hc == TPB
                float hv = b1[k];
#pragma unroll
                for (int q = 0; q < 4; q++) hv += __ldcg(&g_hqp[q][b * Hc + k]);
                sl[k] = hv;
            }
            __syncthreads();
            int warp = tid >> 5, lane = tid & 31;
#pragma unroll
            for (int ni = 0; ni < 4; ni++) {
                int n = warp + ni * 16;
                const float* ep = g_encproj + (size_t)(b * Nc + n) * Hc;
                float acc = 0.f;
#pragma unroll 4
                for (int k = lane; k < Hc; k += 32) {
                    float v = sl[k] + ep[k];
                    acc = fmaf(fmaxf(v, 0.f), Va[k], acc);
                }
#pragma unroll
                for (int o = 16; o; o >>= 1) acc += __shfl_down_sync(0xffffffffu, acc, o);
                if (lane == 0) sred[n] = acc + bVa[0];
            }
            __syncthreads();
            if (tid < 64) {
                float m = sred[tid];
#pragma unroll
                for (int o = 16; o; o >>= 1) m = fmaxf(m, __shfl_xor_sync(0xffffffffu, m, o));
                if (lane == 0) s_aux[tid >> 5] = m;
            }
            __syncthreads();
            if (tid < 64) {
                float M = fmaxf(s_aux[0], s_aux[1]);
                float e = expf(sred[tid] - M);
                sred[tid] = e;
                float ss = e;
#pragma unroll
                for (int o = 16; o; o >>= 1) ss += __shfl_xor_sync(0xffffffffu, ss, o);
                if (lane == 0) s_aux[2 + (tid >> 5)] = ss;
            }
            __syncthreads();
            if (tid < 64) {
                float wv = sred[tid] / (s_aux[2] + s_aux[3]);
                sred[tid] = wv;
                if (sub == 0)
                    dout[AOFF + (size_t)b * Tc * Nc + (size_t)t * Nc + tid] = wv;
            }
            __syncthreads();
            if (tid < 320) {
                int f = sub * 320 + tid;
                const float* fb = feat + (size_t)b * Nc * Fc + f;
                float acc = 0.f;
#pragma unroll 8
                for (int n = 0; n < 64; n++) acc = fmaf(fb[(size_t)n * Fc], sred[n], acc);
                float gl = bg[f];
#pragma unroll
                for (int q = 0; q < 4; q++) gl += __ldcg(&g_glp[q][b * Fc + f]);
                g_ctx[b * Fc + f] = acc * sigf(gl);
            }
        }
        gridbar();

        // ===== P3: gates x/ctx part: 16 tiles x 14 K-chunks(128) = 224 units =====
        for (int u = bid; u < 224; u += NBLK) {
            int tile = u / 14, kch = u % 14;
            unit_gemm<128, 1>(sw, sb, Wx, G4, kch * 128, tile * 128, G4,
                              g_x, Ec, g_gp[4 + kch] + tile * 128, G4, tid);
        }
        gridbar();

        // ===== P3b: LSTM pointwise (reduce 18 partials) =====
        if (bid < 32) {
            int id = bid * TPB + tid;
            int b = id >> 9, j = id & 511;
            float gi = blstm[j], gf = blstm[Hc + j], gg = blstm[2 * Hc + j], go = blstm[3 * Hc + j];
#pragma unroll
            for (int p = 0; p < 18; p++) {
                const float* gp = g_gp[p] + (size_t)b * G4;
                gi += __ldcg(&gp[j]);
                gf += __ldcg(&gp[Hc + j]);
                gg += __ldcg(&gp[2 * Hc + j]);
                go += __ldcg(&gp[3 * Hc + j]);
            }
            float cprev = g_c[rp][b * Hc + j];
            float iv = sigf(gi), fv = sigf(gf), gv = tanhf(gg), ov = sigf(go);
            float c2 = fv * cprev + iv * gv;
            float h2 = ov * tanhf(c2);
            g_c[wp][b * Hc + j] = c2;
            g_h[wp][b * Hc + j] = h2;
            if (t == Tc - 1) {
                dout[HOFF + b * Hc + j] = h2;
                dout[COFF + b * Hc + j] = c2;
            }
        }
        gridbar();

        // ===== P4: logits partials: 79 tiles x 8 K-chunks(64) = 632 units =====
        for (int u = bid; u < 632; u += NBLK) {
            int tile = u >> 3, kq = u & 7;
            unit_gemm<64, 0>(sw, sb, Wout, Vc, kq * 64, tile * 128, Vc,
                             g_h[wp], Hc, g_lp[kq] + tile * 128, LPW, tid);
        }
        gridbar();

        // ===== P5: reduce 8 partials + bias + store logits + per-tile argmax =====
        if (bid < NT79) {
            int tile = bid;
            int ct = tid & 31, bg4 = (tid >> 5) * 2;
            int c4 = ct * 4;
#pragma unroll
            for (int bb = 0; bb < 2; bb++) {
                int b = bg4 + bb;
#pragma unroll
                for (int j = 0; j < 4; j++) {
                    int col = tile * 128 + c4 + j;
                    bool valid = (col < Vc);
                    float v = -INFINITY;
                    if (valid) {
                        v = bout[col];
#pragma unroll
                        for (int q = 0; q < 8; q++)
                            v += __ldcg(&g_lp[q][(size_t)b * LPW + col]);
                        dout[(size_t)b * Tc * Vc + (size_t)t * Vc + col] = v;
                    }
                    sl[b * 128 + c4 + j] = v;
                }
            }
            __syncthreads();
            if (tid < 32) {
                int b = tid;
                float bv = -INFINITY; int bi = 0;
#pragma unroll 8
                for (int cq = 0; cq < 128; cq++) {
                    float v = sl[b * 128 + cq];
                    if (v > bv) { bv = v; bi = tile * 128 + cq; }
                }
                g_pbv[tile * 32 + b] = bv;
                g_pbi[tile * 32 + b] = bi;
            }
        }
        gridbar();
    }
}

// ---------------- launcher ----------------
extern "C" void kernel_launch(void* const* d_in, const int* in_sizes, int n_in,
                              void* d_out, int out_size) {
    int off = (n_in > 2 && in_sizes[2] == 1) ? 1 : 0;
    const float* feat  = (const float*)d_in[0];
    const float* emb   = (const float*)d_in[2 + off];
    const float* W1    = (const float*)d_in[3 + off];
    const float* b1    = (const float*)d_in[4 + off];
    const float* W2    = (const float*)d_in[5 + off];
    const float* b2    = (const float*)d_in[6 + off];
    const float* Va    = (const float*)d_in[7 + off];
    const float* bVa   = (const float*)d_in[8 + off];
    const float* Wh    = (const float*)d_in[9 + off];
    const float* bh    = (const float*)d_in[10 + off];
    const float* Wc    = (const float*)d_in[11 + off];
    const float* bc    = (const float*)d_in[12 + off];
    const float* Wg    = (const float*)d_in[13 + off];
    const float* bg    = (const float*)d_in[14 + off];
    const float* Wx    = (const float*)d_in[15 + off];
    const float* Whh   = (const float*)d_in[16 + off];
    const float* blstm = (const float*)d_in[17 + off];
    const float* Wout  = (const float*)d_in[18 + off];
    const float* bout  = (const float*)d_in[19 + off];
    float* out = (float*)d_out;

    cudaFuncSetAttribute(k_persist, cudaFuncAttributeMaxDynamicSharedMemorySize, SMEM_BYTES);

    k_mean<<<160, 256>>>(feat, emb);
    k_h0c0<<<16, 256>>>(Wh, bh, Wc, bc);
    k_encproj<<<dim3(32, 8), 256>>>(feat, W2, b2);
    k_persist<<<NBLK, TPB, SMEM_BYTES>>>(feat, emb, W1, b1, Va, bVa, Wg, bg,
                                         Wx, Whh, blstm, Wout, bout, out);
}

// round 9
// speedup vs baseline: 4.5057x; 1.0185x over previous
#include <cuda_runtime.h>
#include <cuda_bf16.h>
#include <math.h>

#define Bc 32
#define Nc 64
#define Fc 1280
#define Hc 512
#define Ec 512
#define Vc 10000
#define Tc 80
#define SOSc 1
#define G4 2048
#define NBLK 148
#define TPB 512
#define LPW 10112
#define NT79 79

typedef unsigned long long ull;

// ---------------- device scratch ----------------
__device__ float g_h[2][Bc * Hc];
__device__ float g_c[2][Bc * Hc];
__device__ float g_x[Bc * Ec];
__device__ float g_hqp[4][Bc * Hc];    // hq partials (K-split 4)
__device__ float g_glp[4][Bc * Fc];    // glin partials (K-split 4)
__device__ float g_ctx[Bc * Fc];
__device__ float g_encproj[Bc * Nc * Hc];
__device__ float g_mean[Bc * Fc];
__device__ float g_gp[18][Bc * G4];    // gates partials: 0..3 h-part, 4..17 x-part
__device__ float g_lp[8][Bc * LPW];    // logits partials (K-split 8)
__device__ float g_pbv[NT79 * Bc];
__device__ int   g_pbi[NT79 * Bc];
__device__ unsigned g_bar;

#define HOFF ((size_t)Bc * Tc * Vc)
#define COFF (HOFF + (size_t)Bc * Hc)
#define AOFF (COFF + (size_t)Bc * Hc)

// dynamic smem carve (floats): sw 16384 | sb 4608 | sl 4096 | sred 512 | sredi 512 | aux 8
#define SMEM_FLOATS (16384 + 4608 + 4096 + 512 + 512 + 8)
#define SMEM_BYTES (SMEM_FLOATS * 4)

__device__ __forceinline__ float sigf(float x) { return 1.0f / (1.0f + expf(-x)); }

__device__ __forceinline__ ull pk2(float x) {
    ull r; asm("mov.b64 %0,{%1,%1};" : "=l"(r) : "r"(__float_as_uint(x))); return r;
}
__device__ __forceinline__ void fma2(ull& d, ull a, ull b) {
    asm("fma.rn.f32x2 %0,%1,%2,%0;" : "+l"(d) : "l"(a), "l"(b));
}
__device__ __forceinline__ ull add2(ull a, ull b) {
    ull d; asm("add.rn.f32x2 %0,%1,%2;" : "=l"(d) : "l"(a), "l"(b)); return d;
}
__device__ __forceinline__ float2 un2(ull v) {
    unsigned lo, hi; asm("mov.b64 {%0,%1},%2;" : "=r"(lo), "=r"(hi) : "l"(v));
    float2 f; f.x = __uint_as_float(lo); f.y = __uint_as_float(hi); return f;
}

__device__ __forceinline__ void gridbar() {
    __syncthreads();
    if (threadIdx.x == 0) {
        __threadfence();
        unsigned t = atomicAdd(&g_bar, 1u) + 1u;
        unsigned target = ((t + NBLK - 1u) / NBLK) * NBLK;
        while (*((volatile unsigned*)&g_bar) < target) __nanosleep(64);
        __threadfence();
    }
    __syncthreads();
}

// ================= unified SMEM-tile GEMM unit =================
// C_partial[32 x 128cols] = op[32 x NKK] @ W[NKK x 128cols] -> dstp.
// Weights staged ONCE into sw (kills LDG redundancy); operand transposed into
// sb[kk*36 + b]. Two kk-planes (tid>>8) reduced via add.rn.f32x2.
// Warp lane tile: 8 col-threads x 4 batch-groups => weight LDS.128 = 1 phase
// (128B span, 4-lane broadcast), operand LDS.128 = 1 phase (64B span).
template <int NKK, int SRCMODE>
__device__ __forceinline__ void unit_gemm(
    float* sw, float* sb,
    const float* __restrict__ W, size_t ldw, int kc, int col0, int maxc,
    const float* __restrict__ src, int sstride,
    float* dstp, size_t dst_stride, int tid)
{
    // stage weights: NKK rows x 128 cols, coalesced LDG.128 rows
    {
        int maxc4 = maxc - 4;
#pragma unroll
        for (int e = tid; e < NKK * 32; e += TPB) {
            int kk = e >> 5, cc = (e & 31) << 2;
            int cg = col0 + cc; if (cg > maxc4) cg = maxc4;
            *(float4*)&sw[kk * 128 + cc] =
                *(const float4*)&W[(size_t)(kc + kk) * ldw + cg];
        }
    }
    // stage operand transposed: warp reads 32 consecutive k of one batch row
    {
        int warp = tid >> 5, lane = tid & 31;
#pragma unroll
        for (int idx = warp; idx < NKK; idx += 16) {
            int b = idx & 31, kkc = (idx >> 5) << 5;
            int k = kc + kkc + lane;
            float v;
            if (SRCMODE == 0) v = __ldcg(&src[b * sstride + k]);
            else v = (k < Ec) ? __ldcg(&g_x[b * Ec + k])
                              : __ldcg(&g_ctx[b * Fc + (k - Ec)]);
            sb[(kkc + lane) * 36 + b] = v;
        }
    }
    __syncthreads();
    const int ks = tid >> 8;            // K-plane
    const int lt = tid & 255;           // 256 threads/plane = 8 warps
    const int wrp = lt >> 5, lane = lt & 31;
    const int ct = (wrp & 3) * 8 + (lane & 7);   // col-thread 0..31 (8 per warp)
    const int bg = (wrp >> 2) * 4 + (lane >> 3); // batch-group 0..7 (4 per warp)
    const int c4 = ct << 2, b4 = bg << 2;
    ull a0 = 0, a1 = 0, a2 = 0, a3 = 0, a4 = 0, a5 = 0, a6 = 0, a7 = 0;
    {
        const float* swp = sw + ks * (NKK / 2) * 128 + c4;
        const float* sbp = sb + ks * (NKK / 2) * 36 + b4;
#pragma unroll 8
        for (int kk = 0; kk < NKK / 2; kk++) {
            ulonglong2 w = *(const ulonglong2*)(swp + kk * 128);
            float4 bb = *(const float4*)(sbp + kk * 36);
            ull p0 = pk2(bb.x), p1 = pk2(bb.y), p2 = pk2(bb.z), p3 = pk2(bb.w);
            fma2(a0, w.x, p0); fma2(a1, w.y, p0);
            fma2(a2, w.x, p1); fma2(a3, w.y, p1);
            fma2(a4, w.x, p2); fma2(a5, w.y, p2);
            fma2(a6, w.x, p3); fma2(a7, w.y, p3);
        }
    }
    __syncthreads();
    ull* red = (ull*)sw;
    if (ks == 1) {
        red[lt * 8 + 0] = a0; red[lt * 8 + 1] = a1;
        red[lt * 8 + 2] = a2; red[lt * 8 + 3] = a3;
        red[lt * 8 + 4] = a4; red[lt * 8 + 5] = a5;
        red[lt * 8 + 6] = a6; red[lt * 8 + 7] = a7;
    }
    __syncthreads();
    if (ks == 0) {
        a0 = add2(a0, red[lt * 8 + 0]); a1 = add2(a1, red[lt * 8 + 1]);
        a2 = add2(a2, red[lt * 8 + 2]); a3 = add2(a3, red[lt * 8 + 3]);
        a4 = add2(a4, red[lt * 8 + 4]); a5 = add2(a5, red[lt * 8 + 5]);
        a6 = add2(a6, red[lt * 8 + 6]); a7 = add2(a7, red[lt * 8 + 7]);
        float2 q0, q1;
        q0 = un2(a0); q1 = un2(a1);
        *(float4*)&dstp[(size_t)(b4 + 0) * dst_stride + c4] = make_float4(q0.x, q0.y, q1.x, q1.y);
        q0 = un2(a2); q1 = un2(a3);
        *(float4*)&dstp[(size_t)(b4 + 1) * dst_stride + c4] = make_float4(q0.x, q0.y, q1.x, q1.y);
        q0 = un2(a4); q1 = un2(a5);
        *(float4*)&dstp[(size_t)(b4 + 2) * dst_stride + c4] = make_float4(q0.x, q0.y, q1.x, q1.y);
        q0 = un2(a6); q1 = un2(a7);
        *(float4*)&dstp[(size_t)(b4 + 3) * dst_stride + c4] = make_float4(q0.x, q0.y, q1.x, q1.y);
    }
    __syncthreads();
}

// ---------------- init kernels ----------------
__global__ void k_mean(const float* __restrict__ feat, const float* __restrict__ emb) {
    int idx = blockIdx.x * blockDim.x + threadIdx.x;
    if (idx == 0) g_bar = 0u;
    if (idx < Bc * Ec) g_x[idx] = emb[(size_t)SOSc * Ec + (idx % Ec)];
    if (idx >= Bc * Fc) return;
    int b = idx / Fc, f = idx % Fc;
    float s = 0.f;
    const float* p = feat + (size_t)b * Nc * Fc + f;
#pragma unroll 8
    for (int n = 0; n < Nc; n++) s += p[(size_t)n * Fc];
    g_mean[idx] = s * (1.0f / 64.0f);
}

__global__ void k_h0c0(const float* __restrict__ Wh, const float* __restrict__ bh,
                       const float* __restrict__ Wc, const float* __restrict__ bc) {
    __shared__ __align__(16) float sm[64 * 36];
    int tid = threadIdx.x;
    int colg = blockIdx.x * 64 + (tid & 63);
    int bgrp = tid >> 6;
    float acc[8] = {0, 0, 0, 0, 0, 0, 0, 0};
    const float* W; float bias; float* dst;
    if (colg < Hc) { W = Wh + colg; bias = bh[colg]; dst = g_h[0] + colg; }
    else { W = Wc + (colg - Hc); bias = bc[colg - Hc]; dst = g_c[0] + (colg - Hc); }
    for (int kc = 0; kc < Fc; kc += 64) {
        __syncthreads();
        for (int e = tid; e < 2048; e += 256) {
            int kk = e >> 5, b = e & 31;
            sm[kk * 36 + b] = g_mean[b * Fc + kc + kk];
        }
        __syncthreads();
#pragma unroll 8
        for (int kk = 0; kk < 64; kk++) {
            float w = W[(size_t)(kc + kk) * Hc];
            const float* xr = &sm[kk * 36 + bgrp * 8];
#pragma unroll
            for (int i = 0; i < 8; i++) acc[i] = fmaf(xr[i], w, acc[i]);
        }
    }
#pragma unroll
    for (int i = 0; i < 8; i++) dst[(bgrp * 8 + i) * Hc] = acc[i] + bias;
}

__global__ void k_encproj(const float* __restrict__ feat, const float* __restrict__ W2,
                          const float* __restrict__ b2) {
    int tid = threadIdx.x;
    int rowbase = blockIdx.x * 64;
    int colbase = blockIdx.y * 64;
    int col = colbase + (tid & 63);
    int rgrp = tid >> 6;
    float acc[16];
#pragma unroll
    for (int i = 0; i < 16; i++) acc[i] = 0.f;
    __shared__ float As[64][33];
    __shared__ float Ws[32][65];
    for (int kc = 0; kc < Fc; kc += 32) {
        for (int e = tid; e < 64 * 32; e += 256) {
            int r = e >> 5, kk = e & 31;
            As[r][kk] = feat[(size_t)(rowbase + r) * Fc + kc + kk];
        }
        for (int e = tid; e < 32 * 64; e += 256) {
            int kk = e >> 6, c = e & 63;
            Ws[kk][c] = W2[(size_t)(kc + kk) * Hc + colbase + c];
        }
        __syncthreads();
#pragma unroll 8
        for (int kk = 0; kk < 32; kk++) {
            float w = Ws[kk][tid & 63];
#pragma unroll
            for (int i = 0; i < 16; i++) acc[i] += As[rgrp * 16 + i][kk] * w;
        }
        __syncthreads();
    }
    float bb = b2[col];
#pragma unroll
    for (int i = 0; i < 16; i++)
        g_encproj[(size_t)(rowbase + rgrp * 16 + i) * Hc + col] = acc[i] + bb;
}

// ---------------- persistent kernel ----------------
__global__ void __launch_bounds__(TPB, 1) k_persist(
    const float* __restrict__ feat, const float* __restrict__ emb,
    const float* __restrict__ W1, const float* __restrict__ b1,
    const float* __restrict__ Va, const float* __restrict__ bVa,
    const float* __restrict__ Wg, const float* __restrict__ bg,
    const float* __restrict__ Wx, const float* __restrict__ Whh,
    const float* __restrict__ blstm, const float* __restrict__ Wout,
    const float* __restrict__ bout, float* __restrict__ dout)
{
    extern __shared__ __align__(16) float dsm[];
    float* sw   = dsm;                    // 16384 floats (64KB)
    float* sb   = dsm + 16384;            // 4608 floats
    float* sl   = sb + 4608;              // 4096 floats
    float* sred = sl + 4096;              // 512
    int*  sredi = (int*)(sred + 512);     // 512
    float* s_aux = (float*)(sredi + 512); // 8

    const int bid = blockIdx.x;
    const int tid = threadIdx.x;

    for (int t = 0; t < Tc; t++) {
        const int rp = t & 1, wp = rp ^ 1;

        // ===== P1: argmax(t-1)->x | hq/glin partials | gates h-part partials =====
        if (bid < 16) {
            if (t > 0) {
                int half = tid >> 8, lt = tid & 255;
                int b = bid * 2 + half;
                float bv = -INFINITY; int bi = 0x7fffffff;
                if (lt < NT79) {
                    bv = __ldcg(&g_pbv[lt * 32 + b]);
                    bi = __ldcg(&g_pbi[lt * 32 + b]);
                }
                sred[tid] = bv; sredi[tid] = bi;
                __syncthreads();
                for (int o = 128; o; o >>= 1) {
                    if (lt < o) {
                        if (sred[tid + o] > sred[tid] ||
                            (sred[tid + o] == sred[tid] && sredi[tid + o] < sredi[tid])) {
                            sred[tid] = sred[tid + o];
                            sredi[tid] = sredi[tid + o];
                        }
                    }
                    __syncthreads();
                }
                int best = sredi[half * 256];
                for (int e = lt; e < Ec; e += 256)
                    g_x[b * Ec + e] = emb[(size_t)best * Ec + e];
            }
        } else if (bid < 72) {
            int u = bid - 16, tile = u >> 2, kq = u & 3;
            int col0 = tile * 128, kc = kq * 128;
            if (tile < 4)
                unit_gemm<128, 0>(sw, sb, W1, Hc, kc, col0, Hc,
                                  g_h[rp], Hc, g_hqp[kq] + col0, Hc, tid);
            else
                unit_gemm<128, 0>(sw, sb, Wg, Fc, kc, col0 - 512, Fc,
                                  g_h[rp], Hc, g_glp[kq] + (col0 - 512), Fc, tid);
        } else if (bid < 136) {
            int u = bid - 72, tile = u >> 2, kq = u & 3;
            unit_gemm<128, 0>(sw, sb, Whh, G4, kq * 128, tile * 128, G4,
                              g_h[rp], Hc, g_gp[kq] + tile * 128, G4, tid);
        }
        gridbar();

        // ===== P2: attention (4 blocks per batch) =====
        if (bid < 128) {
            int b = bid >> 2, sub = bid & 3;
            {
                int k = tid;  // Hc == TPB
                float hv = b1[k];
#pragma unroll
                for (int q = 0; q < 4; q++) hv += __ldcg(&g_hqp[q][b * Hc + k]);
                sl[k] = hv;
            }
            __syncthreads();
            int warp = tid >> 5, lane = tid & 31;
#pragma unroll
            for (int ni = 0; ni < 4; ni++) {
                int n = warp + ni * 16;
                const float* ep = g_encproj + (size_t)(b * Nc + n) * Hc;
                float acc = 0.f;
#pragma unroll 4
                for (int k = lane; k < Hc; k += 32) {
                    float v = sl[k] + ep[k];
                    acc = fmaf(fmaxf(v, 0.f), Va[k], acc);
                }
#pragma unroll
                for (int o = 16; o; o >>= 1) acc += __shfl_down_sync(0xffffffffu, acc, o);
                if (lane == 0) sred[n] = acc + bVa[0];
            }
            __syncthreads();
            if (tid < 64) {
                float m = sred[tid];
#pragma unroll
                for (int o = 16; o; o >>= 1) m = fmaxf(m, __shfl_xor_sync(0xffffffffu, m, o));
                if (lane == 0) s_aux[tid >> 5] = m;
            }
            __syncthreads();
            if (tid < 64) {
                float M = fmaxf(s_aux[0], s_aux[1]);
                float e = expf(sred[tid] - M);
                sred[tid] = e;
                float ss = e;
#pragma unroll
                for (int o = 16; o; o >>= 1) ss += __shfl_xor_sync(0xffffffffu, ss, o);
                if (lane == 0) s_aux[2 + (tid >> 5)] = ss;
            }
            __syncthreads();
            if (tid < 64) {
                float wv = sred[tid] / (s_aux[2] + s_aux[3]);
                sred[tid] = wv;
                if (sub == 0)
                    dout[AOFF + (size_t)b * Tc * Nc + (size_t)t * Nc + tid] = wv;
            }
            __syncthreads();
            if (tid < 320) {
                int f = sub * 320 + tid;
                const float* fb = feat + (size_t)b * Nc * Fc + f;
                float acc = 0.f;
#pragma unroll 8
                for (int n = 0; n < 64; n++) acc = fmaf(fb[(size_t)n * Fc], sred[n], acc);
                float gl = bg[f];
#pragma unroll
                for (int q = 0; q < 4; q++) gl += __ldcg(&g_glp[q][b * Fc + f]);
                g_ctx[b * Fc + f] = acc * sigf(gl);
            }
        }
        gridbar();

        // ===== P3: gates x/ctx part: 16 tiles x 14 K-chunks(128) = 224 units =====
        for (int u = bid; u < 224; u += NBLK) {
            int tile = u / 14, kch = u % 14;
            unit_gemm<128, 1>(sw, sb, Wx, G4, kch * 128, tile * 128, G4,
                              g_x, Ec, g_gp[4 + kch] + tile * 128, G4, tid);
        }
        gridbar();

        // ===== P3b: LSTM pointwise (reduce 18 partials) =====
        if (bid < 32) {
            int id = bid * TPB + tid;
            int b = id >> 9, j = id & 511;
            float gi = blstm[j], gf = blstm[Hc + j], gg = blstm[2 * Hc + j], go = blstm[3 * Hc + j];
#pragma unroll
            for (int p = 0; p < 18; p++) {
                const float* gp = g_gp[p] + (size_t)b * G4;
                gi += __ldcg(&gp[j]);
                gf += __ldcg(&gp[Hc + j]);
                gg += __ldcg(&gp[2 * Hc + j]);
                go += __ldcg(&gp[3 * Hc + j]);
            }
            float cprev = g_c[rp][b * Hc + j];
            float iv = sigf(gi), fv = sigf(gf), gv = tanhf(gg), ov = sigf(go);
            float c2 = fv * cprev + iv * gv;
            float h2 = ov * tanhf(c2);
            g_c[wp][b * Hc + j] = c2;
            g_h[wp][b * Hc + j] = h2;
            if (t == Tc - 1) {
                dout[HOFF + b * Hc + j] = h2;
                dout[COFF + b * Hc + j] = c2;
            }
        }
        gridbar();

        // ===== P4: logits partials: 79 tiles x 8 K-chunks(64) = 632 units =====
        for (int u = bid; u < 632; u += NBLK) {
            int tile = u >> 3, kq = u & 7;
            unit_gemm<64, 0>(sw, sb, Wout, Vc, kq * 64, tile * 128, Vc,
                             g_h[wp], Hc, g_lp[kq] + tile * 128, LPW, tid);
        }
        gridbar();

        // ===== P5: reduce 8 partials + bias + store logits + per-tile argmax =====
        if (bid < NT79) {
            int tile = bid;
            int ct = tid & 31, bg4 = (tid >> 5) * 2;
            int c4 = ct * 4;
#pragma unroll
            for (int bb = 0; bb < 2; bb++) {
                int b = bg4 + bb;
#pragma unroll
                for (int j = 0; j < 4; j++) {
                    int col = tile * 128 + c4 + j;
                    bool valid = (col < Vc);
                    float v = -INFINITY;
                    if (valid) {
                        v = bout[col];
#pragma unroll
                        for (int q = 0; q < 8; q++)
                            v += __ldcg(&g_lp[q][(size_t)b * LPW + col]);
                        dout[(size_t)b * Tc * Vc + (size_t)t * Vc + col] = v;
                    }
                    sl[b * 128 + c4 + j] = v;
                }
            }
            __syncthreads();
            if (tid < 32) {
                int b = tid;
                float bv = -INFINITY; int bi = 0;
#pragma unroll 8
                for (int cq = 0; cq < 128; cq++) {
                    float v = sl[b * 128 + cq];
                    if (v > bv) { bv = v; bi = tile * 128 + cq; }
                }
                g_pbv[tile * 32 + b] = bv;
                g_pbi[tile * 32 + b] = bi;
            }
        }
        gridbar();
    }
}

// ---------------- launcher ----------------
extern "C" void kernel_launch(void* const* d_in, const int* in_sizes, int n_in,
                              void* d_out, int out_size) {
    int off = (n_in > 2 && in_sizes[2] == 1) ? 1 : 0;
    const float* feat  = (const float*)d_in[0];
    const float* emb   = (const float*)d_in[2 + off];
    const float* W1    = (const float*)d_in[3 + off];
    const float* b1    = (const float*)d_in[4 + off];
    const float* W2    = (const float*)d_in[5 + off];
    const float* b2    = (const float*)d_in[6 + off];
    const float* Va    = (const float*)d_in[7 + off];
    const float* bVa   = (const float*)d_in[8 + off];
    const float* Wh    = (const float*)d_in[9 + off];
    const float* bh    = (const float*)d_in[10 + off];
    const float* Wc    = (const float*)d_in[11 + off];
    const float* bc    = (const float*)d_in[12 + off];
    const float* Wg    = (const float*)d_in[13 + off];
    const float* bg    = (const float*)d_in[14 + off];
    const float* Wx    = (const float*)d_in[15 + off];
    const float* Whh   = (const float*)d_in[16 + off];
    const float* blstm = (const float*)d_in[17 + off];
    const float* Wout  = (const float*)d_in[18 + off];
    const float* bout  = (const float*)d_in[19 + off];
    float* out = (float*)d_out;

    cudaFuncSetAttribute(k_persist, cudaFuncAttributeMaxDynamicSharedMemorySize, SMEM_BYTES);

    k_mean<<<160, 256>>>(feat, emb);
    k_h0c0<<<16, 256>>>(Wh, bh, Wc, bc);
    k_encproj<<<dim3(32, 8), 256>>>(feat, W2, b2);
    k_persist<<<NBLK, TPB, SMEM_BYTES>>>(feat, emb, W1, b1, Va, bVa, Wg, bg,
                                         Wx, Whh, blstm, Wout, bout, out);
}

// round 10
// speedup vs baseline: 5.4304x; 1.2052x over previous
#include <cuda_runtime.h>
#include <cuda_bf16.h>
#include <math.h>

#define Bc 32
#define Nc 64
#define Fc 1280
#define Hc 512
#define Ec 512
#define Vc 10000
#define Tc 80
#define SOSc 1
#define G4 2048
#define NBLK 148
#define TPB 512
#define NT79 79

typedef unsigned long long ull;

// ---------------- device scratch ----------------
__device__ float g_h[2][Bc * Hc];
__device__ float g_c[2][Bc * Hc];
__device__ float g_x[Bc * Ec];
__device__ float g_hq[Bc * Hc];        // full hq (bias included)
__device__ float g_glin[Bc * Fc];      // full glin (bias included)
__device__ float g_gh[Bc * G4];        // full gates h-part
__device__ float g_ctx[Bc * Fc];
__device__ float g_encproj[Bc * Nc * Hc];
__device__ float g_mean[Bc * Fc];
__device__ float g_gp[14][Bc * G4];    // gates x-part partials (K-split 14)
__device__ float g_pbv[NT79 * Bc];
__device__ int   g_pbi[NT79 * Bc];
__device__ unsigned g_bar;

#define HOFF ((size_t)Bc * Tc * Vc)
#define COFF (HOFF + (size_t)Bc * Hc)
#define AOFF (COFF + (size_t)Bc * Hc)

// dynamic smem carve (floats): sw 16384 | sb 4608 | sl 4096 | sred 512 | sredi 512 | aux 8
#define SMEM_FLOATS (16384 + 4608 + 4096 + 512 + 512 + 8)
#define SMEM_BYTES (SMEM_FLOATS * 4)

__device__ __forceinline__ float sigf(float x) { return 1.0f / (1.0f + expf(-x)); }

__device__ __forceinline__ ull pk2(float x) {
    ull r; asm("mov.b64 %0,{%1,%1};" : "=l"(r) : "r"(__float_as_uint(x))); return r;
}
__device__ __forceinline__ void fma2(ull& d, ull a, ull b) {
    asm("fma.rn.f32x2 %0,%1,%2,%0;" : "+l"(d) : "l"(a), "l"(b));
}
__device__ __forceinline__ ull add2(ull a, ull b) {
    ull d; asm("add.rn.f32x2 %0,%1,%2;" : "=l"(d) : "l"(a), "l"(b)); return d;
}
__device__ __forceinline__ float2 un2(ull v) {
    unsigned lo, hi; asm("mov.b64 {%0,%1},%2;" : "=r"(lo), "=r"(hi) : "l"(v));
    float2 f; f.x = __uint_as_float(lo); f.y = __uint_as_float(hi); return f;
}

__device__ __forceinline__ void gridbar() {
    __syncthreads();
    if (threadIdx.x == 0) {
        __threadfence();
        unsigned t = atomicAdd(&g_bar, 1u) + 1u;
        unsigned target = ((t + NBLK - 1u) / NBLK) * NBLK;
        while (*((volatile unsigned*)&g_bar) < target) __nanosleep(64);
        __threadfence();
    }
    __syncthreads();
}

// ================= full-K (512) tile unit: 128 cols, no global K-split =================
// 4 K-planes (tid>>7), each plane handles 32 kk of each of the 4 staged 128-k chunks.
// Thread tile: 4 cols x 8 batches; operand batch-pairs consumed as packed ull (no movs).
// Plane-reduce once at the end; LOGITS path adds bias, stores dout, does tile argmax.
template <bool LOGITS>
__device__ __forceinline__ void unit_fk(
    float* sw, float* sb, float* sl,
    const float* __restrict__ W, size_t ldw, int col0, int maxc,
    const float* __restrict__ hsrc, const float* __restrict__ bias,
    float* dstp, size_t dst_stride,
    float* __restrict__ dout, int t, int tile, int tid)
{
    const int ks = tid >> 7;            // plane 0..3
    const int lt = tid & 127;
    const int wrp = lt >> 5, lane = lt & 31;
    const int ct = wrp * 8 + (lane & 7);    // 0..31 col-thread
    const int bg = lane >> 3;               // 0..3 batch-group (8 batches)
    const int c4 = ct << 2, b8 = bg << 3;
    ull A[16];
#pragma unroll
    for (int i = 0; i < 16; i++) A[i] = 0;
    const int maxc4 = maxc - 4;
    for (int ch = 0; ch < 4; ch++) {
        int kc = ch * 128;
#pragma unroll
        for (int e = tid; e < 4096; e += TPB) {
            int kk = e >> 5, cc = (e & 31) << 2;
            int cg = col0 + cc; if (cg > maxc4) cg = maxc4;
            *(float4*)&sw[kk * 128 + cc] = *(const float4*)&W[(size_t)(kc + kk) * ldw + cg];
        }
        {
            int warp = tid >> 5, lane2 = tid & 31;
#pragma unroll
            for (int idx = warp; idx < 128; idx += 16) {
                int b = idx & 31, kkc = (idx >> 5) << 5;
                sb[(kkc + lane2) * 36 + b] = __ldcg(&hsrc[b * Hc + kc + kkc + lane2]);
            }
        }
        __syncthreads();
        {
            const float* swp = sw + (ks * 32) * 128 + c4;
            const float* sbp = sb + (ks * 32) * 36 + b8;
#pragma unroll 8
            for (int kk = 0; kk < 32; kk++) {
                float4 w = *(const float4*)(swp + kk * 128);
                ulonglong2 b01 = *(const ulonglong2*)(sbp + kk * 36);
                ulonglong2 b23 = *(const ulonglong2*)(sbp + kk * 36 + 4);
                ull w0 = pk2(w.x), w1 = pk2(w.y), w2 = pk2(w.z), w3 = pk2(w.w);
                fma2(A[0],  w0, b01.x); fma2(A[1],  w1, b01.x);
                fma2(A[2],  w2, b01.x); fma2(A[3],  w3, b01.x);
                fma2(A[4],  w0, b01.y); fma2(A[5],  w1, b01.y);
                fma2(A[6],  w2, b01.y); fma2(A[7],  w3, b01.y);
                fma2(A[8],  w0, b23.x); fma2(A[9],  w1, b23.x);
                fma2(A[10], w2, b23.x); fma2(A[11], w3, b23.x);
                fma2(A[12], w0, b23.y); fma2(A[13], w1, b23.y);
                fma2(A[14], w2, b23.y); fma2(A[15], w3, b23.y);
            }
        }
        __syncthreads();
    }
    // plane reduce (A[bp*4 + c])
    ull* red = (ull*)sw;
    if (ks > 0) {
#pragma unroll
        for (int i = 0; i < 16; i++) red[((ks - 1) * 128 + lt) * 16 + i] = A[i];
    }
    __syncthreads();
    if (ks == 0) {
#pragma unroll
        for (int p = 0; p < 3; p++)
#pragma unroll
            for (int i = 0; i < 16; i++)
                A[i] = add2(A[i], red[(p * 128 + lt) * 16 + i]);
        float vals[8][4];
#pragma unroll
        for (int bp = 0; bp < 4; bp++)
#pragma unroll
            for (int c = 0; c < 4; c++) {
                float2 q = un2(A[bp * 4 + c]);
                vals[bp * 2 + 0][c] = q.x;
                vals[bp * 2 + 1][c] = q.y;
            }
        if (!LOGITS) {
            float4 bb = make_float4(0.f, 0.f, 0.f, 0.f);
            if (bias) bb = *(const float4*)&bias[c4];
#pragma unroll
            for (int i = 0; i < 8; i++) {
                int b = b8 + i;
                *(float4*)&dstp[(size_t)b * dst_stride + c4] =
                    make_float4(vals[i][0] + bb.x, vals[i][1] + bb.y,
                                vals[i][2] + bb.z, vals[i][3] + bb.w);
            }
        } else {
#pragma unroll
            for (int i = 0; i < 8; i++) {
                int b = b8 + i;
#pragma unroll
                for (int c = 0; c < 4; c++) {
                    int col = col0 + c4 + c;
                    float v = -INFINITY;
                    if (col < Vc) {
                        v = vals[i][c] + bias[c4 + c];
                        dout[(size_t)b * Tc * Vc + (size_t)t * Vc + col] = v;
                    }
                    sl[b * 128 + c4 + c] = v;
                }
            }
        }
    }
    if (LOGITS) {
        __syncthreads();
        if (tid < 32) {
            int b = tid;
            float bv = -INFINITY; int bi = 0;
#pragma unroll 8
            for (int cq = 0; cq < 128; cq++) {
                float v = sl[b * 128 + cq];
                if (v > bv) { bv = v; bi = col0 + cq; }
            }
            g_pbv[tile * 32 + b] = bv;
            g_pbi[tile * 32 + b] = bi;
        }
    }
}

// ================= K-chunk partial unit (for gates x-part), from R8 =================
template <int NKK>
__device__ __forceinline__ void unit_gemm(
    float* sw, float* sb,
    const float* __restrict__ W, size_t ldw, int kc, int col0,
    float* dstp, size_t dst_stride, int tid)
{
#pragma unroll
    for (int e = tid; e < NKK * 32; e += TPB) {
        int kk = e >> 5, cc = (e & 31) << 2;
        *(float4*)&sw[kk * 128 + cc] =
            *(const float4*)&W[(size_t)(kc + kk) * ldw + col0 + cc];
    }
    {
        int warp = tid >> 5, lane = tid & 31;
#pragma unroll
        for (int idx = warp; idx < NKK; idx += 16) {
            int b = idx & 31, kkc = (idx >> 5) << 5;
            int k = kc + kkc + lane;
            float v = (k < Ec) ? __ldcg(&g_x[b * Ec + k])
                               : __ldcg(&g_ctx[b * Fc + (k - Ec)]);
            sb[(kkc + lane) * 36 + b] = v;
        }
    }
    __syncthreads();
    const int ks = tid >> 8;
    const int lt = tid & 255;
    const int wrp = lt >> 5, lane = lt & 31;
    const int ct = (wrp & 3) * 8 + (lane & 7);
    const int bg = (wrp >> 2) * 4 + (lane >> 3);
    const int c4 = ct << 2, b4 = bg << 2;
    ull a0 = 0, a1 = 0, a2 = 0, a3 = 0, a4 = 0, a5 = 0, a6 = 0, a7 = 0;
    {
        const float* swp = sw + ks * (NKK / 2) * 128 + c4;
        const float* sbp = sb + ks * (NKK / 2) * 36 + b4;
#pragma unroll 8
        for (int kk = 0; kk < NKK / 2; kk++) {
            ulonglong2 w = *(const ulonglong2*)(swp + kk * 128);
            float4 bb = *(const float4*)(sbp + kk * 36);
            ull p0 = pk2(bb.x), p1 = pk2(bb.y), p2 = pk2(bb.z), p3 = pk2(bb.w);
            fma2(a0, w.x, p0); fma2(a1, w.y, p0);
            fma2(a2, w.x, p1); fma2(a3, w.y, p1);
            fma2(a4, w.x, p2); fma2(a5, w.y, p2);
            fma2(a6, w.x, p3); fma2(a7, w.y, p3);
        }
    }
    __syncthreads();
    ull* red = (ull*)sw;
    if (ks == 1) {
        red[lt * 8 + 0] = a0; red[lt * 8 + 1] = a1;
        red[lt * 8 + 2] = a2; red[lt * 8 + 3] = a3;
        red[lt * 8 + 4] = a4; red[lt * 8 + 5] = a5;
        red[lt * 8 + 6] = a6; red[lt * 8 + 7] = a7;
    }
    __syncthreads();
    if (ks == 0) {
        a0 = add2(a0, red[lt * 8 + 0]); a1 = add2(a1, red[lt * 8 + 1]);
        a2 = add2(a2, red[lt * 8 + 2]); a3 = add2(a3, red[lt * 8 + 3]);
        a4 = add2(a4, red[lt * 8 + 4]); a5 = add2(a5, red[lt * 8 + 5]);
        a6 = add2(a6, red[lt * 8 + 6]); a7 = add2(a7, red[lt * 8 + 7]);
        float2 q0, q1;
        q0 = un2(a0); q1 = un2(a1);
        *(float4*)&dstp[(size_t)(b4 + 0) * dst_stride + c4] = make_float4(q0.x, q0.y, q1.x, q1.y);
        q0 = un2(a2); q1 = un2(a3);
        *(float4*)&dstp[(size_t)(b4 + 1) * dst_stride + c4] = make_float4(q0.x, q0.y, q1.x, q1.y);
        q0 = un2(a4); q1 = un2(a5);
        *(float4*)&dstp[(size_t)(b4 + 2) * dst_stride + c4] = make_float4(q0.x, q0.y, q1.x, q1.y);
        q0 = un2(a6); q1 = un2(a7);
        *(float4*)&dstp[(size_t)(b4 + 3) * dst_stride + c4] = make_float4(q0.x, q0.y, q1.x, q1.y);
    }
    __syncthreads();
}

// ---------------- init kernels ----------------
__global__ void k_mean(const float* __restrict__ feat, const float* __restrict__ emb) {
    int idx = blockIdx.x * blockDim.x + threadIdx.x;
    if (idx == 0) g_bar = 0u;
    if (idx < Bc * Ec) g_x[idx] = emb[(size_t)SOSc * Ec + (idx % Ec)];
    if (idx >= Bc * Fc) return;
    int b = idx / Fc, f = idx % Fc;
    float s = 0.f;
    const float* p = feat + (size_t)b * Nc * Fc + f;
#pragma unroll 8
    for (int n = 0; n < Nc; n++) s += p[(size_t)n * Fc];
    g_mean[idx] = s * (1.0f / 64.0f);
}

__global__ void k_h0c0(const float* __restrict__ Wh, const float* __restrict__ bh,
                       const float* __restrict__ Wc, const float* __restrict__ bc) {
    __shared__ __align__(16) float sm[64 * 36];
    int tid = threadIdx.x;
    int colg = blockIdx.x * 64 + (tid & 63);
    int bgrp = tid >> 6;
    float acc[8] = {0, 0, 0, 0, 0, 0, 0, 0};
    const float* W; float bias; float* dst;
    if (colg < Hc) { W = Wh + colg; bias = bh[colg]; dst = g_h[0] + colg; }
    else { W = Wc + (colg - Hc); bias = bc[colg - Hc]; dst = g_c[0] + (colg - Hc); }
    for (int kc = 0; kc < Fc; kc += 64) {
        __syncthreads();
        for (int e = tid; e < 2048; e += 256) {
            int kk = e >> 5, b = e & 31;
            sm[kk * 36 + b] = g_mean[b * Fc + kc + kk];
        }
        __syncthreads();
#pragma unroll 8
        for (int kk = 0; kk < 64; kk++) {
            float w = W[(size_t)(kc + kk) * Hc];
            const float* xr = &sm[kk * 36 + bgrp * 8];
#pragma unroll
            for (int i = 0; i < 8; i++) acc[i] = fmaf(xr[i], w, acc[i]);
        }
    }
#pragma unroll
    for (int i = 0; i < 8; i++) dst[(bgrp * 8 + i) * Hc] = acc[i] + bias;
}

__global__ void k_encproj(const float* __restrict__ feat, const float* __restrict__ W2,
                          const float* __restrict__ b2) {
    int tid = threadIdx.x;
    int rowbase = blockIdx.x * 64;
    int colbase = blockIdx.y * 64;
    int col = colbase + (tid & 63);
    int rgrp = tid >> 6;
    float acc[16];
#pragma unroll
    for (int i = 0; i < 16; i++) acc[i] = 0.f;
    __shared__ float As[64][33];
    __shared__ float Ws[32][65];
    for (int kc = 0; kc < Fc; kc += 32) {
        for (int e = tid; e < 64 * 32; e += 256) {
            int r = e >> 5, kk = e & 31;
            As[r][kk] = feat[(size_t)(rowbase + r) * Fc + kc + kk];
        }
        for (int e = tid; e < 32 * 64; e += 256) {
            int kk = e >> 6, c = e & 63;
            Ws[kk][c] = W2[(size_t)(kc + kk) * Hc + colbase + c];
        }
        __syncthreads();
#pragma unroll 8
        for (int kk = 0; kk < 32; kk++) {
            float w = Ws[kk][tid & 63];
#pragma unroll
            for (int i = 0; i < 16; i++) acc[i] += As[rgrp * 16 + i][kk] * w;
        }
        __syncthreads();
    }
    float bb = b2[col];
#pragma unroll
    for (int i = 0; i < 16; i++)
        g_encproj[(size_t)(rowbase + rgrp * 16 + i) * Hc + col] = acc[i] + bb;
}

// ---------------- persistent kernel ----------------
__global__ void __launch_bounds__(TPB, 1) k_persist(
    const float* __restrict__ feat, const float* __restrict__ emb,
    const float* __restrict__ W1, const float* __restrict__ b1,
    const float* __restrict__ Va, const float* __restrict__ bVa,
    const float* __restrict__ Wg, const float* __restrict__ bg,
    const float* __restrict__ Wx, const float* __restrict__ Whh,
    const float* __restrict__ blstm, const float* __restrict__ Wout,
    const float* __restrict__ bout, float* __restrict__ dout)
{
    extern __shared__ __align__(16) float dsm[];
    float* sw   = dsm;                    // 16384 floats (64KB)
    float* sb   = dsm + 16384;            // 4608 floats
    float* sl   = sb + 4608;              // 4096 floats
    float* sred = sl + 4096;              // 512
    int*  sredi = (int*)(sred + 512);     // 512
    float* s_aux = (float*)(sredi + 512); // 8

    const int bid = blockIdx.x;
    const int tid = threadIdx.x;

    // ===== pre-loop: hq(0)/glin(0)/gates-h(0) from h(0) =====
    if (bid < 30) {
        int u = bid;
        if (u < 4) {
            int col0 = u * 128;
            unit_fk<false>(sw, sb, sl, W1, Hc, col0, Hc, g_h[0], b1 + col0,
                           g_hq + col0, Hc, nullptr, 0, 0, tid);
        } else if (u < 14) {
            int col0 = (u - 4) * 128;
            unit_fk<false>(sw, sb, sl, Wg, Fc, col0, Fc, g_h[0], bg + col0,
                           g_glin + col0, Fc, nullptr, 0, 0, tid);
        } else {
            int col0 = (u - 14) * 128;
            unit_fk<false>(sw, sb, sl, Whh, G4, col0, G4, g_h[0], nullptr,
                           g_gh + col0, G4, nullptr, 0, 0, tid);
        }
    }
    gridbar();

    for (int t = 0; t < Tc; t++) {
        const int rp = t & 1, wp = rp ^ 1;

        // ===== PHASE A: attention (blocks 0..127) || argmax(t-1)->x (128..147) =====
        if (bid < 128) {
            int b = bid >> 2, sub = bid & 3;
            sl[tid] = __ldcg(&g_hq[b * Hc + tid]);   // Hc == TPB, bias included
            __syncthreads();
            int warp = tid >> 5, lane = tid & 31;
#pragma unroll
            for (int ni = 0; ni < 4; ni++) {
                int n = warp + ni * 16;
                const float* ep = g_encproj + (size_t)(b * Nc + n) * Hc;
                float acc = 0.f;
#pragma unroll 4
                for (int k = lane; k < Hc; k += 32) {
                    float v = sl[k] + ep[k];
                    acc = fmaf(fmaxf(v, 0.f), Va[k], acc);
                }
#pragma unroll
                for (int o = 16; o; o >>= 1) acc += __shfl_down_sync(0xffffffffu, acc, o);
                if (lane == 0) sred[n] = acc + bVa[0];
            }
            __syncthreads();
            if (tid < 64) {
                float m = sred[tid];
#pragma unroll
                for (int o = 16; o; o >>= 1) m = fmaxf(m, __shfl_xor_sync(0xffffffffu, m, o));
                if (lane == 0) s_aux[tid >> 5] = m;
            }
            __syncthreads();
            if (tid < 64) {
                float M = fmaxf(s_aux[0], s_aux[1]);
                float e = expf(sred[tid] - M);
                sred[tid] = e;
                float ss = e;
#pragma unroll
                for (int o = 16; o; o >>= 1) ss += __shfl_xor_sync(0xffffffffu, ss, o);
                if (lane == 0) s_aux[2 + (tid >> 5)] = ss;
            }
            __syncthreads();
            if (tid < 64) {
                float wv = sred[tid] / (s_aux[2] + s_aux[3]);
                sred[tid] = wv;
                if (sub == 0)
                    dout[AOFF + (size_t)b * Tc * Nc + (size_t)t * Nc + tid] = wv;
            }
            __syncthreads();
            if (tid < 320) {
                int f = sub * 320 + tid;
                const float* fb = feat + (size_t)b * Nc * Fc + f;
                float acc = 0.f;
#pragma unroll 8
                for (int n = 0; n < 64; n++) acc = fmaf(fb[(size_t)n * Fc], sred[n], acc);
                float gl = __ldcg(&g_glin[b * Fc + f]);   // bias included
                g_ctx[b * Fc + f] = acc * sigf(gl);
            }
        } else if (t > 0) {
            int i = bid - 128;
            int half = tid >> 8, lt2 = tid & 255;
            int b = (i < 12) ? (2 * i + half) : (24 + (i - 12));
            bool active = (i < 12) || (half == 0);
            float bv = -INFINITY; int bi2 = 0x7fffffff;
            if (active && lt2 < NT79) {
                bv = __ldcg(&g_pbv[lt2 * 32 + b]);
                bi2 = __ldcg(&g_pbi[lt2 * 32 + b]);
            }
            sred[tid] = bv; sredi[tid] = bi2;
            __syncthreads();
            for (int o = 128; o; o >>= 1) {
                if (lt2 < o) {
                    if (sred[tid + o] > sred[tid] ||
                        (sred[tid + o] == sred[tid] && sredi[tid + o] < sredi[tid])) {
                        sred[tid] = sred[tid + o];
                        sredi[tid] = sredi[tid + o];
                    }
                }
                __syncthreads();
            }
            if (active) {
                int best = sredi[half * 256];
                for (int e = lt2; e < Ec; e += 256)
                    g_x[b * Ec + e] = emb[(size_t)best * Ec + e];
            }
        }
        gridbar();

        // ===== PHASE C: gates x/ctx part: 16 tiles x 14 K-chunks(128) = 224 units =====
        for (int u = bid; u < 224; u += NBLK) {
            int tile = u / 14, kch = u % 14;
            unit_gemm<128>(sw, sb, Wx, G4, kch * 128, tile * 128,
                           g_gp[kch] + tile * 128, G4, tid);
        }
        gridbar();

        // ===== PHASE D: LSTM pointwise (g_gh + 14 partials) =====
        if (bid < 32) {
            int id = bid * TPB + tid;
            int b = id >> 9, j = id & 511;
            float gi = blstm[j]          + __ldcg(&g_gh[(size_t)b * G4 + j]);
            float gf = blstm[Hc + j]     + __ldcg(&g_gh[(size_t)b * G4 + Hc + j]);
            float gg = blstm[2 * Hc + j] + __ldcg(&g_gh[(size_t)b * G4 + 2 * Hc + j]);
            float go = blstm[3 * Hc + j] + __ldcg(&g_gh[(size_t)b * G4 + 3 * Hc + j]);
#pragma unroll
            for (int p = 0; p < 14; p++) {
                const float* gp = g_gp[p] + (size_t)b * G4;
                gi += __ldcg(&gp[j]);
                gf += __ldcg(&gp[Hc + j]);
                gg += __ldcg(&gp[2 * Hc + j]);
                go += __ldcg(&gp[3 * Hc + j]);
            }
            float cprev = g_c[rp][b * Hc + j];
            float iv = sigf(gi), fv = sigf(gf), gv = tanhf(gg), ov = sigf(go);
            float c2 = fv * cprev + iv * gv;
            float h2 = ov * tanhf(c2);
            g_c[wp][b * Hc + j] = c2;
            g_h[wp][b * Hc + j] = h2;
            if (t == Tc - 1) {
                dout[HOFF + b * Hc + j] = h2;
                dout[COFF + b * Hc + j] = c2;
            }
        }
        gridbar();

        // ===== PHASE E: logits(t) [79 tiles] || hq/glin/gates-h(t+1) [30 units] =====
        if (bid < NT79) {
            unit_fk<true>(sw, sb, sl, Wout, Vc, bid * 128, Vc, g_h[wp],
                          bout + bid * 128, nullptr, 0, dout, t, bid, tid);
        } else if (bid < 109) {
            int u = bid - NT79;
            if (u < 4) {
                int col0 = u * 128;
                unit_fk<false>(sw, sb, sl, W1, Hc, col0, Hc, g_h[wp], b1 + col0,
                               g_hq + col0, Hc, nullptr, 0, 0, tid);
            } else if (u < 14) {
                int col0 = (u - 4) * 128;
                unit_fk<false>(sw, sb, sl, Wg, Fc, col0, Fc, g_h[wp], bg + col0,
                               g_glin + col0, Fc, nullptr, 0, 0, tid);
            } else {
                int col0 = (u - 14) * 128;
                unit_fk<false>(sw, sb, sl, Whh, G4, col0, G4, g_h[wp], nullptr,
                               g_gh + col0, G4, nullptr, 0, 0, tid);
            }
        }
        gridbar();
    }
}

// ---------------- launcher ----------------
extern "C" void kernel_launch(void* const* d_in, const int* in_sizes, int n_in,
                              void* d_out, int out_size) {
    int off = (n_in > 2 && in_sizes[2] == 1) ? 1 : 0;
    const float* feat  = (const float*)d_in[0];
    const float* emb   = (const float*)d_in[2 + off];
    const float* W1    = (const float*)d_in[3 + off];
    const float* b1    = (const float*)d_in[4 + off];
    const float* W2    = (const float*)d_in[5 + off];
    const float* b2    = (const float*)d_in[6 + off];
    const float* Va    = (const float*)d_in[7 + off];
    const float* bVa   = (const float*)d_in[8 + off];
    const float* Wh    = (const float*)d_in[9 + off];
    const float* bh    = (const float*)d_in[10 + off];
    const float* Wc    = (const float*)d_in[11 + off];
    const float* bc    = (const float*)d_in[12 + off];
    const float* Wg    = (const float*)d_in[13 + off];
    const float* bg    = (const float*)d_in[14 + off];
    const float* Wx    = (const float*)d_in[15 + off];
    const float* Whh   = (const float*)d_in[16 + off];
    const float* blstm = (const float*)d_in[17 + off];
    const float* Wout  = (const float*)d_in[18 + off];
    const float* bout  = (const float*)d_in[19 + off];
    float* out = (float*)d_out;

    cudaFuncSetAttribute(k_persist, cudaFuncAttributeMaxDynamicSharedMemorySize, SMEM_BYTES);

    k_mean<<<160, 256>>>(feat, emb);
    k_h0c0<<<16, 256>>>(Wh, bh, Wc, bc);
    k_encproj<<<dim3(32, 8), 256>>>(feat, W2, b2);
    k_persist<<<NBLK, TPB, SMEM_BYTES>>>(feat, emb, W1, b1, Va, bVa, Wg, bg,
                                         Wx, Whh, blstm, Wout, bout, out);
}